// round 1
// baseline (speedup 1.0000x reference)
#include <cuda_runtime.h>

// ---------------------------------------------------------------------------
// MemoryEfficientAttnBlock: GroupNorm -> window QKV attention -> out proj + res
// B=4, C=512, H=W=64, WS=32 -> 16 windows of n=1024 tokens, 8 heads, d=64.
// All fp32 SIMT (round 1 baseline; tensor cores next round).
// ---------------------------------------------------------------------------

#define BB    4
#define CCH   512
#define HW    4096      // 64*64
#define NHEAD 8
#define DH    64
#define NWIN  16
#define NTOK  1024
#define GRP   32
#define CPG   16        // channels per group

// Scratch (device globals; allocation-free rule)
__device__ float g_hn[BB * CCH * HW];                 // group-normed x, [b][c][hw]
__device__ float g_q[NWIN * NHEAD * NTOK * DH];       // [win][head][n][d]
__device__ float g_k[NWIN * NHEAD * NTOK * DH];
__device__ float g_v[NWIN * NHEAD * NTOK * DH];
__device__ float g_ao[BB * CCH * HW];                 // attention output, [b][c][hw]

// ---------------------------------------------------------------------------
// Kernel 1: GroupNorm.  grid = 128 (b*32 groups), 256 threads.
// ---------------------------------------------------------------------------
__global__ __launch_bounds__(256) void gn_kernel(const float* __restrict__ x,
                                                 const float* __restrict__ scale,
                                                 const float* __restrict__ bias) {
    int b = blockIdx.x >> 5;
    int g = blockIdx.x & 31;
    const float4* xp = (const float4*)(x + (size_t)(b * CCH + g * CPG) * HW);
    float4* yp = (float4*)(g_hn + (size_t)(b * CCH + g * CPG) * HW);
    const int NV = CPG * HW / 4;  // 16384 float4s

    float s = 0.f, s2 = 0.f;
    for (int i = threadIdx.x; i < NV; i += 256) {
        float4 v = xp[i];
        s  += v.x + v.y + v.z + v.w;
        s2 += v.x * v.x + v.y * v.y + v.z * v.z + v.w * v.w;
    }
    __shared__ float rb[2][8];
    #pragma unroll
    for (int o = 16; o; o >>= 1) {
        s  += __shfl_xor_sync(0xffffffffu, s,  o);
        s2 += __shfl_xor_sync(0xffffffffu, s2, o);
    }
    int warp = threadIdx.x >> 5, lane = threadIdx.x & 31;
    if (lane == 0) { rb[0][warp] = s; rb[1][warp] = s2; }
    __syncthreads();
    if (warp == 0) {
        s  = (lane < 8) ? rb[0][lane] : 0.f;
        s2 = (lane < 8) ? rb[1][lane] : 0.f;
        #pragma unroll
        for (int o = 4; o; o >>= 1) {
            s  += __shfl_xor_sync(0xffffffffu, s,  o);
            s2 += __shfl_xor_sync(0xffffffffu, s2, o);
        }
        if (lane == 0) { rb[0][0] = s; rb[1][0] = s2; }
    }
    __syncthreads();
    const float n = (float)(CPG * HW);
    float mu  = rb[0][0] / n;
    float var = rb[1][0] / n - mu * mu;
    float rstd = rsqrtf(var + 1e-6f);

    for (int i = threadIdx.x; i < NV; i += 256) {
        int c = g * CPG + (i >> 10);  // 1024 float4 per channel
        float sc = scale[c] * rstd;
        float bi = bias[c] - mu * sc;
        float4 v = xp[i];
        v.x = v.x * sc + bi; v.y = v.y * sc + bi;
        v.z = v.z * sc + bi; v.w = v.w * sc + bi;
        yp[i] = v;
    }
}

// ---------------------------------------------------------------------------
// Kernel 2: fused QKV 1x1 conv.  grid = (64 h-rows, 8 heads, 4 b), 256 thr.
// Block tile: 64 pixels (one h row) x 64 out channels (one head), k-step 16.
// Each thread: 4x4 micro-tile x 3 matrices.
// Writes q/k/v to [win][head][n][d].
// ---------------------------------------------------------------------------
__global__ __launch_bounds__(256) void qkv_kernel(
    const float* __restrict__ wq, const float* __restrict__ bq,
    const float* __restrict__ wk, const float* __restrict__ bk,
    const float* __restrict__ wv, const float* __restrict__ bv) {
    __shared__ __align__(16) float sX[16][68];   // [c][pixel]
    __shared__ float sW[3][64][17];              // [m][o][c]

    int h    = blockIdx.x;
    int head = blockIdx.y;
    int b    = blockIdx.z;
    int t  = threadIdx.x;
    int tx = t & 15, ty = t >> 4;   // tx -> o group, ty -> pixel group

    float acc[3][4][4];
    #pragma unroll
    for (int m = 0; m < 3; m++)
        #pragma unroll
        for (int i = 0; i < 4; i++)
            #pragma unroll
            for (int j = 0; j < 4; j++) acc[m][i][j] = 0.f;

    const float* xbase = g_hn + (size_t)b * CCH * HW + h * 64;
    const float* wbs[3] = { wq + (size_t)head * 64 * CCH,
                            wk + (size_t)head * 64 * CCH,
                            wv + (size_t)head * 64 * CCH };

    for (int cs = 0; cs < 32; cs++) {
        int c0 = cs * 16;
        {   // load X tile [16 c][64 p] — one float4 per thread
            int p4 = t & 15, cl = t >> 4;
            float4 v = *(const float4*)(xbase + (size_t)(c0 + cl) * HW + p4 * 4);
            *(float4*)&sX[cl][p4 * 4] = v;
        }
        {   // load W tiles [64 o][16 c] — one float4 per thread per matrix
            int ol = t >> 2, c4 = t & 3;
            #pragma unroll
            for (int m = 0; m < 3; m++) {
                float4 v = *(const float4*)(wbs[m] + (size_t)ol * CCH + c0 + c4 * 4);
                sW[m][ol][c4 * 4 + 0] = v.x;
                sW[m][ol][c4 * 4 + 1] = v.y;
                sW[m][ol][c4 * 4 + 2] = v.z;
                sW[m][ol][c4 * 4 + 3] = v.w;
            }
        }
        __syncthreads();
        #pragma unroll
        for (int cc = 0; cc < 16; cc++) {
            float xv[4];
            #pragma unroll
            for (int i = 0; i < 4; i++) xv[i] = sX[cc][ty * 4 + i];
            #pragma unroll
            for (int m = 0; m < 3; m++) {
                float wv4[4];
                #pragma unroll
                for (int j = 0; j < 4; j++) wv4[j] = sW[m][tx * 4 + j][cc];
                #pragma unroll
                for (int i = 0; i < 4; i++)
                    #pragma unroll
                    for (int j = 0; j < 4; j++)
                        acc[m][i][j] += xv[i] * wv4[j];
            }
        }
        __syncthreads();
    }

    // write out: pixel (h, w=ty*4+i), channel d = tx*4+j of this head
    int wh = h >> 5, w1 = h & 31;
    float bq4[4], bk4[4], bv4[4];
    #pragma unroll
    for (int j = 0; j < 4; j++) {
        bq4[j] = bq[head * 64 + tx * 4 + j];
        bk4[j] = bk[head * 64 + tx * 4 + j];
        bv4[j] = bv[head * 64 + tx * 4 + j];
    }
    #pragma unroll
    for (int i = 0; i < 4; i++) {
        int w   = ty * 4 + i;
        int win = b * 4 + wh * 2 + (w >> 5);
        int nn  = w1 * 32 + (w & 31);
        size_t base = (((size_t)win * NHEAD + head) * NTOK + nn) * DH + tx * 4;
        float4 oq = { acc[0][i][0] + bq4[0], acc[0][i][1] + bq4[1],
                      acc[0][i][2] + bq4[2], acc[0][i][3] + bq4[3] };
        float4 ok = { acc[1][i][0] + bk4[0], acc[1][i][1] + bk4[1],
                      acc[1][i][2] + bk4[2], acc[1][i][3] + bk4[3] };
        float4 ov = { acc[2][i][0] + bv4[0], acc[2][i][1] + bv4[1],
                      acc[2][i][2] + bv4[2], acc[2][i][3] + bv4[3] };
        *(float4*)(g_q + base) = oq;
        *(float4*)(g_k + base) = ok;
        *(float4*)(g_v + base) = ov;
    }
}

// ---------------------------------------------------------------------------
// Kernel 3: windowed flash attention.
// grid = (16 q-tiles, 8 heads, 16 windows), 128 threads.
// q-tile = 64 rows; loop 32 k-tiles of 32 rows. Online softmax.
// Thread map: ry = t/8 (4 q-rows each), cx = t%8 (4 k-cols / 8 d-cols each).
// ---------------------------------------------------------------------------
__global__ __launch_bounds__(128) void attn_kernel() {
    __shared__ float sQ[64 * 65];                 // Q [64][65]; reused as output stage
    __shared__ float sKP[64 * 33];                // K [32][65] (2080) / P [64][33] (2112)
    __shared__ __align__(16) float sV[32 * 68];   // V [32][68]

    int qt   = blockIdx.x;
    int head = blockIdx.y;
    int win  = blockIdx.z;
    int t  = threadIdx.x;
    int cx = t & 7, ry = t >> 3;

    size_t hb = ((size_t)win * NHEAD + head) * NTOK * DH;

    // load Q tile (pre-scaled by 1/sqrt(64))
    for (int idx = t; idx < 1024; idx += 128) {   // 1024 float4
        int r = idx >> 4, d4 = idx & 15;
        float4 v = *(const float4*)(g_q + hb + (size_t)(qt * 64 + r) * DH + d4 * 4);
        sQ[r * 65 + d4 * 4 + 0] = v.x * 0.125f;
        sQ[r * 65 + d4 * 4 + 1] = v.y * 0.125f;
        sQ[r * 65 + d4 * 4 + 2] = v.z * 0.125f;
        sQ[r * 65 + d4 * 4 + 3] = v.w * 0.125f;
    }

    float m[4], l[4], out[4][8];
    #pragma unroll
    for (int i = 0; i < 4; i++) {
        m[i] = -1e30f; l[i] = 0.f;
        #pragma unroll
        for (int j = 0; j < 8; j++) out[i][j] = 0.f;
    }

    for (int kt = 0; kt < 32; kt++) {
        // load K,V tiles (32 rows x 64 d)
        for (int idx = t; idx < 512; idx += 128) {
            int kc = idx >> 4, d4 = idx & 15;
            size_t gsrc = hb + (size_t)(kt * 32 + kc) * DH + d4 * 4;
            float4 kv4 = *(const float4*)(g_k + gsrc);
            sKP[kc * 65 + d4 * 4 + 0] = kv4.x;
            sKP[kc * 65 + d4 * 4 + 1] = kv4.y;
            sKP[kc * 65 + d4 * 4 + 2] = kv4.z;
            sKP[kc * 65 + d4 * 4 + 3] = kv4.w;
            float4 vv4 = *(const float4*)(g_v + gsrc);
            *(float4*)&sV[kc * 68 + d4 * 4] = vv4;
        }
        __syncthreads();

        // scores: 4 q-rows x 4 k-cols per thread
        float s[4][4];
        #pragma unroll
        for (int i = 0; i < 4; i++)
            #pragma unroll
            for (int j = 0; j < 4; j++) s[i][j] = 0.f;
        #pragma unroll 8
        for (int d = 0; d < 64; d++) {
            float qv[4], kv[4];
            #pragma unroll
            for (int i = 0; i < 4; i++) qv[i] = sQ[(ry * 4 + i) * 65 + d];
            #pragma unroll
            for (int j = 0; j < 4; j++) kv[j] = sKP[(cx * 4 + j) * 65 + d];
            #pragma unroll
            for (int i = 0; i < 4; i++)
                #pragma unroll
                for (int j = 0; j < 4; j++) s[i][j] += qv[i] * kv[j];
        }

        // online softmax per row (8 threads share a row -> shuffle over 8 lanes)
        float alpha[4];
        #pragma unroll
        for (int i = 0; i < 4; i++) {
            float tm = fmaxf(fmaxf(s[i][0], s[i][1]), fmaxf(s[i][2], s[i][3]));
            tm = fmaxf(tm, __shfl_xor_sync(0xffffffffu, tm, 1));
            tm = fmaxf(tm, __shfl_xor_sync(0xffffffffu, tm, 2));
            tm = fmaxf(tm, __shfl_xor_sync(0xffffffffu, tm, 4));
            float mn = fmaxf(m[i], tm);
            float ps = 0.f;
            #pragma unroll
            for (int j = 0; j < 4; j++) {
                s[i][j] = __expf(s[i][j] - mn);
                ps += s[i][j];
            }
            ps += __shfl_xor_sync(0xffffffffu, ps, 1);
            ps += __shfl_xor_sync(0xffffffffu, ps, 2);
            ps += __shfl_xor_sync(0xffffffffu, ps, 4);
            float al = __expf(m[i] - mn);
            l[i] = l[i] * al + ps;
            m[i] = mn;
            alpha[i] = al;
        }

        __syncthreads();   // done reading K region
        #pragma unroll
        for (int i = 0; i < 4; i++)
            #pragma unroll
            for (int j = 0; j < 4; j++)
                sKP[(ry * 4 + i) * 33 + cx * 4 + j] = s[i][j];
        __syncthreads();   // P visible

        // out += P @ V  (4 rows x 8 d-cols per thread), rescale by alpha first
        #pragma unroll
        for (int i = 0; i < 4; i++)
            #pragma unroll
            for (int j = 0; j < 8; j++) out[i][j] *= alpha[i];
        #pragma unroll 4
        for (int k = 0; k < 32; k++) {
            float pv[4];
            #pragma unroll
            for (int i = 0; i < 4; i++) pv[i] = sKP[(ry * 4 + i) * 33 + k];
            float4 va = *(const float4*)&sV[k * 68 + cx * 8];
            float4 vb = *(const float4*)&sV[k * 68 + cx * 8 + 4];
            float vv[8] = { va.x, va.y, va.z, va.w, vb.x, vb.y, vb.z, vb.w };
            #pragma unroll
            for (int i = 0; i < 4; i++)
                #pragma unroll
                for (int j = 0; j < 8; j++) out[i][j] += pv[i] * vv[j];
        }
        __syncthreads();   // before next tile overwrites sKP/sV
    }

    // finalize and stage into sQ for coalesced transpose-write
    #pragma unroll
    for (int i = 0; i < 4; i++) {
        float inv = 1.0f / l[i];
        #pragma unroll
        for (int j = 0; j < 8; j++)
            sQ[(ry * 4 + i) * 65 + cx * 8 + j] = out[i][j] * inv;
    }
    __syncthreads();

    int b  = win >> 2;
    int wh = (win >> 1) & 1;
    int ww = win & 1;
    for (int idx = t; idx < 4096; idx += 128) {
        int d = idx >> 6, r = idx & 63;
        int nn = qt * 64 + r;
        int h = wh * 32 + (nn >> 5);
        int w = ww * 32 + (nn & 31);
        g_ao[((size_t)b * CCH + head * 64 + d) * HW + h * 64 + w] = sQ[r * 65 + d];
    }
}

// ---------------------------------------------------------------------------
// Kernel 4: out projection + bias + residual.  grid = (64, 8, 4), 256 thr.
// ---------------------------------------------------------------------------
__global__ __launch_bounds__(256) void oproj_kernel(
    const float* __restrict__ x, const float* __restrict__ wo,
    const float* __restrict__ bo, float* __restrict__ out) {
    __shared__ __align__(16) float sX[16][68];
    __shared__ float sW[64][17];
    __shared__ float sO[64][65];   // [o][p] staging

    int h  = blockIdx.x;
    int ot = blockIdx.y;
    int b  = blockIdx.z;
    int t  = threadIdx.x;
    int tx = t & 15, ty = t >> 4;

    float acc[4][4];
    #pragma unroll
    for (int i = 0; i < 4; i++)
        #pragma unroll
        for (int j = 0; j < 4; j++) acc[i][j] = 0.f;

    const float* abase = g_ao + (size_t)b * CCH * HW + h * 64;
    const float* wbase = wo + (size_t)ot * 64 * CCH;

    for (int cs = 0; cs < 32; cs++) {
        int c0 = cs * 16;
        {
            int p4 = t & 15, cl = t >> 4;
            float4 v = *(const float4*)(abase + (size_t)(c0 + cl) * HW + p4 * 4);
            *(float4*)&sX[cl][p4 * 4] = v;
        }
        {
            int ol = t >> 2, c4 = t & 3;
            float4 v = *(const float4*)(wbase + (size_t)ol * CCH + c0 + c4 * 4);
            sW[ol][c4 * 4 + 0] = v.x;
            sW[ol][c4 * 4 + 1] = v.y;
            sW[ol][c4 * 4 + 2] = v.z;
            sW[ol][c4 * 4 + 3] = v.w;
        }
        __syncthreads();
        #pragma unroll
        for (int cc = 0; cc < 16; cc++) {
            float xv[4], wv4[4];
            #pragma unroll
            for (int i = 0; i < 4; i++) xv[i] = sX[cc][ty * 4 + i];
            #pragma unroll
            for (int j = 0; j < 4; j++) wv4[j] = sW[tx * 4 + j][cc];
            #pragma unroll
            for (int i = 0; i < 4; i++)
                #pragma unroll
                for (int j = 0; j < 4; j++)
                    acc[i][j] += xv[i] * wv4[j];
        }
        __syncthreads();
    }

    // stage [o][p] then coalesced write with residual + bias
    #pragma unroll
    for (int i = 0; i < 4; i++)
        #pragma unroll
        for (int j = 0; j < 4; j++)
            sO[tx * 4 + j][ty * 4 + i] = acc[i][j];
    __syncthreads();

    const float* xres = x + ((size_t)b * CCH + ot * 64) * HW + h * 64;
    float* ob = out + ((size_t)b * CCH + ot * 64) * HW + h * 64;
    for (int idx = t; idx < 4096; idx += 256) {
        int ol = idx >> 6, pl = idx & 63;
        ob[(size_t)ol * HW + pl] =
            sO[ol][pl] + xres[(size_t)ol * HW + pl] + bo[ot * 64 + ol];
    }
}

// ---------------------------------------------------------------------------
extern "C" void kernel_launch(void* const* d_in, const int* in_sizes, int n_in,
                              void* d_out, int out_size) {
    (void)in_sizes; (void)n_in; (void)out_size;
    const float* x  = (const float*)d_in[0];
    const float* ns = (const float*)d_in[1];
    const float* nb = (const float*)d_in[2];
    const float* wq = (const float*)d_in[3];
    const float* bq = (const float*)d_in[4];
    const float* wk = (const float*)d_in[5];
    const float* bk = (const float*)d_in[6];
    const float* wv = (const float*)d_in[7];
    const float* bv = (const float*)d_in[8];
    const float* wo = (const float*)d_in[9];
    const float* bo = (const float*)d_in[10];
    float* out = (float*)d_out;

    gn_kernel<<<128, 256>>>(x, ns, nb);
    qkv_kernel<<<dim3(64, 8, 4), 256>>>(wq, bq, wk, bk, wv, bv);
    attn_kernel<<<dim3(16, 8, 16), 128>>>();
    oproj_kernel<<<dim3(64, 8, 4), 256>>>(x, wo, bo, out);
}

// round 2
// speedup vs baseline: 1.1097x; 1.1097x over previous
#include <cuda_runtime.h>

// ---------------------------------------------------------------------------
// MemoryEfficientAttnBlock: GroupNorm -> window QKV attention -> out proj + res
// B=4, C=512, H=W=64, WS=32 -> 16 windows of n=1024 tokens, 8 heads, d=64.
// fp32 SIMT, round 2: all inner loops restructured for LDS.128 / conflict-free
// shared access (R1 ncu: L1 pipe 85%, fma 43% -> shared-bound).
// ---------------------------------------------------------------------------

#define BB    4
#define CCH   512
#define HW    4096      // 64*64
#define NHEAD 8
#define DH    64
#define NWIN  16
#define NTOK  1024
#define CPG   16        // channels per group

// Scratch (device globals; allocation-free rule)
__device__ float g_hn[BB * CCH * HW];                 // group-normed x, [b][c][hw]
__device__ float g_q[NWIN * NHEAD * NTOK * DH];       // [win][head][n][d]
__device__ float g_k[NWIN * NHEAD * NTOK * DH];
__device__ float g_v[NWIN * NHEAD * NTOK * DH];
__device__ float g_ao[BB * CCH * HW];                 // attention output, [b][c][hw]

// ---------------------------------------------------------------------------
// Kernel 1: GroupNorm.  grid = 128 (b*32 groups), 256 threads.
// ---------------------------------------------------------------------------
__global__ __launch_bounds__(256) void gn_kernel(const float* __restrict__ x,
                                                 const float* __restrict__ scale,
                                                 const float* __restrict__ bias) {
    int b = blockIdx.x >> 5;
    int g = blockIdx.x & 31;
    const float4* xp = (const float4*)(x + (size_t)(b * CCH + g * CPG) * HW);
    float4* yp = (float4*)(g_hn + (size_t)(b * CCH + g * CPG) * HW);
    const int NV = CPG * HW / 4;  // 16384 float4s

    float s = 0.f, s2 = 0.f;
    for (int i = threadIdx.x; i < NV; i += 256) {
        float4 v = xp[i];
        s  += v.x + v.y + v.z + v.w;
        s2 += v.x * v.x + v.y * v.y + v.z * v.z + v.w * v.w;
    }
    __shared__ float rb[2][8];
    #pragma unroll
    for (int o = 16; o; o >>= 1) {
        s  += __shfl_xor_sync(0xffffffffu, s,  o);
        s2 += __shfl_xor_sync(0xffffffffu, s2, o);
    }
    int warp = threadIdx.x >> 5, lane = threadIdx.x & 31;
    if (lane == 0) { rb[0][warp] = s; rb[1][warp] = s2; }
    __syncthreads();
    if (warp == 0) {
        s  = (lane < 8) ? rb[0][lane] : 0.f;
        s2 = (lane < 8) ? rb[1][lane] : 0.f;
        #pragma unroll
        for (int o = 4; o; o >>= 1) {
            s  += __shfl_xor_sync(0xffffffffu, s,  o);
            s2 += __shfl_xor_sync(0xffffffffu, s2, o);
        }
        if (lane == 0) { rb[0][0] = s; rb[1][0] = s2; }
    }
    __syncthreads();
    const float n = (float)(CPG * HW);
    float mu  = rb[0][0] / n;
    float var = rb[1][0] / n - mu * mu;
    float rstd = rsqrtf(var + 1e-6f);

    for (int i = threadIdx.x; i < NV; i += 256) {
        int c = g * CPG + (i >> 10);
        float sc = scale[c] * rstd;
        float bi = bias[c] - mu * sc;
        float4 v = xp[i];
        v.x = v.x * sc + bi; v.y = v.y * sc + bi;
        v.z = v.z * sc + bi; v.w = v.w * sc + bi;
        yp[i] = v;
    }
}

// ---------------------------------------------------------------------------
// Kernel 2: fused QKV 1x1 conv.  grid = (64 h-rows, 8 heads, 4 b), 256 thr.
// Weight tiles stored TRANSPOSED in smem ([c][o]) so both operands of the
// micro-kernel are contiguous float4 LDS.128 (12 FFMA per LDS.128).
// ---------------------------------------------------------------------------
__global__ __launch_bounds__(256) void qkv_kernel(
    const float* __restrict__ wq, const float* __restrict__ bq,
    const float* __restrict__ wk, const float* __restrict__ bk,
    const float* __restrict__ wv, const float* __restrict__ bv) {
    __shared__ __align__(16) float sX[16][68];      // [c][pixel]
    __shared__ __align__(16) float sWt[3][16][68];  // [m][c][o]  (transposed)

    int h    = blockIdx.x;
    int head = blockIdx.y;
    int b    = blockIdx.z;
    int t  = threadIdx.x;
    int tx = t & 15, ty = t >> 4;   // tx -> o group, ty -> pixel group

    float acc[3][4][4];
    #pragma unroll
    for (int m = 0; m < 3; m++)
        #pragma unroll
        for (int i = 0; i < 4; i++)
            #pragma unroll
            for (int j = 0; j < 4; j++) acc[m][i][j] = 0.f;

    const float* xbase = g_hn + (size_t)b * CCH * HW + h * 64;
    const float* wbs[3] = { wq + (size_t)head * 64 * CCH,
                            wk + (size_t)head * 64 * CCH,
                            wv + (size_t)head * 64 * CCH };

    for (int cs = 0; cs < 32; cs++) {
        int c0 = cs * 16;
        {   // X tile [16 c][64 p] — one float4 per thread
            int p4 = t & 15, cl = t >> 4;
            float4 v = *(const float4*)(xbase + (size_t)(c0 + cl) * HW + p4 * 4);
            *(float4*)&sX[cl][p4 * 4] = v;
        }
        {   // W tiles, transposed into [c][o]
            int ol = t >> 2, c4 = t & 3;
            #pragma unroll
            for (int m = 0; m < 3; m++) {
                float4 v = *(const float4*)(wbs[m] + (size_t)ol * CCH + c0 + c4 * 4);
                sWt[m][c4 * 4 + 0][ol] = v.x;
                sWt[m][c4 * 4 + 1][ol] = v.y;
                sWt[m][c4 * 4 + 2][ol] = v.z;
                sWt[m][c4 * 4 + 3][ol] = v.w;
            }
        }
        __syncthreads();
        #pragma unroll 4
        for (int cc = 0; cc < 16; cc++) {
            float4 xv = *(const float4*)&sX[cc][ty * 4];   // broadcast per phase
            #pragma unroll
            for (int m = 0; m < 3; m++) {
                float4 wv4 = *(const float4*)&sWt[m][cc][tx * 4];  // conflict-free
                acc[m][0][0] += xv.x * wv4.x; acc[m][0][1] += xv.x * wv4.y;
                acc[m][0][2] += xv.x * wv4.z; acc[m][0][3] += xv.x * wv4.w;
                acc[m][1][0] += xv.y * wv4.x; acc[m][1][1] += xv.y * wv4.y;
                acc[m][1][2] += xv.y * wv4.z; acc[m][1][3] += xv.y * wv4.w;
                acc[m][2][0] += xv.z * wv4.x; acc[m][2][1] += xv.z * wv4.y;
                acc[m][2][2] += xv.z * wv4.z; acc[m][2][3] += xv.z * wv4.w;
                acc[m][3][0] += xv.w * wv4.x; acc[m][3][1] += xv.w * wv4.y;
                acc[m][3][2] += xv.w * wv4.z; acc[m][3][3] += xv.w * wv4.w;
            }
        }
        __syncthreads();
    }

    int wh = h >> 5, w1 = h & 31;
    float bq4[4], bk4[4], bv4[4];
    #pragma unroll
    for (int j = 0; j < 4; j++) {
        bq4[j] = bq[head * 64 + tx * 4 + j];
        bk4[j] = bk[head * 64 + tx * 4 + j];
        bv4[j] = bv[head * 64 + tx * 4 + j];
    }
    #pragma unroll
    for (int i = 0; i < 4; i++) {
        int w   = ty * 4 + i;
        int win = b * 4 + wh * 2 + (w >> 5);
        int nn  = w1 * 32 + (w & 31);
        size_t base = (((size_t)win * NHEAD + head) * NTOK + nn) * DH + tx * 4;
        float4 oq = { acc[0][i][0] + bq4[0], acc[0][i][1] + bq4[1],
                      acc[0][i][2] + bq4[2], acc[0][i][3] + bq4[3] };
        float4 ok = { acc[1][i][0] + bk4[0], acc[1][i][1] + bk4[1],
                      acc[1][i][2] + bk4[2], acc[1][i][3] + bk4[3] };
        float4 ov = { acc[2][i][0] + bv4[0], acc[2][i][1] + bv4[1],
                      acc[2][i][2] + bv4[2], acc[2][i][3] + bv4[3] };
        *(float4*)(g_q + base) = oq;
        *(float4*)(g_k + base) = ok;
        *(float4*)(g_v + base) = ov;
    }
}

// ---------------------------------------------------------------------------
// Kernel 3: windowed flash attention.
// grid = (16 q-tiles, 8 heads, 16 windows), 128 threads.
// q-tile 64 rows; 32 k-tiles of 32 rows, online softmax.
// Score cols per thread: cx + 8j  -> conflict-free K LDS.128.
// Out d-cols per thread: {cx*4..+3, 32+cx*4..+3} -> conflict-free V LDS.128.
// ---------------------------------------------------------------------------
__global__ __launch_bounds__(128) void attn_kernel() {
    __shared__ __align__(16) float sQ[64 * 68];   // Q, stride 68
    __shared__ __align__(16) float sKV[2 * 32 * 68]; // K then V; reused for output (stride 65)
    __shared__ __align__(16) float sP[64 * 36];   // P, stride 36

    float* sK = sKV;
    float* sV = sKV + 32 * 68;

    int qt   = blockIdx.x;
    int head = blockIdx.y;
    int win  = blockIdx.z;
    int t  = threadIdx.x;
    int cx = t & 7, ry = t >> 3;

    size_t hb = ((size_t)win * NHEAD + head) * NTOK * DH;

    // load Q tile (pre-scaled by 1/sqrt(64))
    for (int idx = t; idx < 1024; idx += 128) {   // 1024 float4
        int r = idx >> 4, d4 = idx & 15;
        float4 v = *(const float4*)(g_q + hb + (size_t)(qt * 64 + r) * DH + d4 * 4);
        v.x *= 0.125f; v.y *= 0.125f; v.z *= 0.125f; v.w *= 0.125f;
        *(float4*)&sQ[r * 68 + d4 * 4] = v;
    }

    float m[4], l[4], out[4][8];
    #pragma unroll
    for (int i = 0; i < 4; i++) {
        m[i] = -1e30f; l[i] = 0.f;
        #pragma unroll
        for (int j = 0; j < 8; j++) out[i][j] = 0.f;
    }

    for (int kt = 0; kt < 32; kt++) {
        // load K,V tiles (32 rows x 64 d)
        for (int idx = t; idx < 512; idx += 128) {
            int kc = idx >> 4, d4 = idx & 15;
            size_t gsrc = hb + (size_t)(kt * 32 + kc) * DH + d4 * 4;
            *(float4*)&sK[kc * 68 + d4 * 4] = *(const float4*)(g_k + gsrc);
            *(float4*)&sV[kc * 68 + d4 * 4] = *(const float4*)(g_v + gsrc);
        }
        __syncthreads();

        // scores: 4 q-rows x 4 k-cols (cols cx+8j) per thread, float4 over d
        float s[4][4];
        #pragma unroll
        for (int i = 0; i < 4; i++)
            #pragma unroll
            for (int j = 0; j < 4; j++) s[i][j] = 0.f;
        #pragma unroll 4
        for (int d4 = 0; d4 < 16; d4++) {
            float4 qv[4];
            #pragma unroll
            for (int i = 0; i < 4; i++)
                qv[i] = *(const float4*)&sQ[(ry * 4 + i) * 68 + d4 * 4];
            #pragma unroll
            for (int j = 0; j < 4; j++) {
                float4 kv = *(const float4*)&sK[(cx + 8 * j) * 68 + d4 * 4];
                #pragma unroll
                for (int i = 0; i < 4; i++)
                    s[i][j] += qv[i].x * kv.x + qv[i].y * kv.y
                             + qv[i].z * kv.z + qv[i].w * kv.w;
            }
        }

        // online softmax per row (8 lanes share a row)
        float alpha[4];
        #pragma unroll
        for (int i = 0; i < 4; i++) {
            float tm = fmaxf(fmaxf(s[i][0], s[i][1]), fmaxf(s[i][2], s[i][3]));
            tm = fmaxf(tm, __shfl_xor_sync(0xffffffffu, tm, 1));
            tm = fmaxf(tm, __shfl_xor_sync(0xffffffffu, tm, 2));
            tm = fmaxf(tm, __shfl_xor_sync(0xffffffffu, tm, 4));
            float mn = fmaxf(m[i], tm);
            float ps = 0.f;
            #pragma unroll
            for (int j = 0; j < 4; j++) {
                s[i][j] = __expf(s[i][j] - mn);
                ps += s[i][j];
            }
            ps += __shfl_xor_sync(0xffffffffu, ps, 1);
            ps += __shfl_xor_sync(0xffffffffu, ps, 2);
            ps += __shfl_xor_sync(0xffffffffu, ps, 4);
            float al = __expf(m[i] - mn);
            l[i] = l[i] * al + ps;
            m[i] = mn;
            alpha[i] = al;
        }

        // stage P (producer/consumer lanes are within one warp)
        __syncwarp();
        #pragma unroll
        for (int i = 0; i < 4; i++)
            #pragma unroll
            for (int j = 0; j < 4; j++)
                sP[(ry * 4 + i) * 36 + cx + 8 * j] = s[i][j];
        __syncwarp();

        // out += P @ V   (out d-cols: cx*4+{0..3} and 32+cx*4+{0..3})
        #pragma unroll
        for (int i = 0; i < 4; i++)
            #pragma unroll
            for (int j = 0; j < 8; j++) out[i][j] *= alpha[i];
        #pragma unroll 2
        for (int k4 = 0; k4 < 8; k4++) {
            float4 pv[4];
            #pragma unroll
            for (int i = 0; i < 4; i++)
                pv[i] = *(const float4*)&sP[(ry * 4 + i) * 36 + k4 * 4];
            #pragma unroll
            for (int kk = 0; kk < 4; kk++) {
                float4 va = *(const float4*)&sV[(k4 * 4 + kk) * 68 + cx * 4];
                float4 vb = *(const float4*)&sV[(k4 * 4 + kk) * 68 + 32 + cx * 4];
                #pragma unroll
                for (int i = 0; i < 4; i++) {
                    float p = (kk == 0) ? pv[i].x : (kk == 1) ? pv[i].y
                            : (kk == 2) ? pv[i].z : pv[i].w;
                    out[i][0] += p * va.x; out[i][1] += p * va.y;
                    out[i][2] += p * va.z; out[i][3] += p * va.w;
                    out[i][4] += p * vb.x; out[i][5] += p * vb.y;
                    out[i][6] += p * vb.z; out[i][7] += p * vb.w;
                }
            }
        }
        __syncthreads();   // before next tile overwrites sK/sV
    }

    // finalize; stage [row][d] with odd stride 65 into sKV for conflict-free
    // transposed readout
    float* sOut = sKV;
    #pragma unroll
    for (int i = 0; i < 4; i++) {
        float inv = 1.0f / l[i];
        int row = ry * 4 + i;
        #pragma unroll
        for (int j = 0; j < 4; j++) {
            sOut[row * 65 + cx * 4 + j]      = out[i][j]     * inv;
            sOut[row * 65 + 32 + cx * 4 + j] = out[i][j + 4] * inv;
        }
    }
    __syncthreads();

    int b  = win >> 2;
    int wh = (win >> 1) & 1;
    int ww = win & 1;
    for (int idx = t; idx < 4096; idx += 128) {
        int d = idx >> 6, r = idx & 63;
        int nn = qt * 64 + r;
        int h = wh * 32 + (nn >> 5);
        int w = ww * 32 + (nn & 31);
        g_ao[((size_t)b * CCH + head * 64 + d) * HW + h * 64 + w] = sOut[r * 65 + d];
    }
}

// ---------------------------------------------------------------------------
// Kernel 4: out projection + bias + residual.  grid = (64, 8, 4), 256 thr.
// Transposed weight tile in smem -> both operands LDS.128.
// ---------------------------------------------------------------------------
__global__ __launch_bounds__(256) void oproj_kernel(
    const float* __restrict__ x, const float* __restrict__ wo,
    const float* __restrict__ bo, float* __restrict__ out) {
    __shared__ __align__(16) float sX[16][68];
    __shared__ __align__(16) float sWt[16][68];   // [c][o] transposed
    __shared__ float sO[64][65];                  // [o][p] staging

    int h  = blockIdx.x;
    int ot = blockIdx.y;
    int b  = blockIdx.z;
    int t  = threadIdx.x;
    int tx = t & 15, ty = t >> 4;

    float acc[4][4];
    #pragma unroll
    for (int i = 0; i < 4; i++)
        #pragma unroll
        for (int j = 0; j < 4; j++) acc[i][j] = 0.f;

    const float* abase = g_ao + (size_t)b * CCH * HW + h * 64;
    const float* wbase = wo + (size_t)ot * 64 * CCH;

    for (int cs = 0; cs < 32; cs++) {
        int c0 = cs * 16;
        {
            int p4 = t & 15, cl = t >> 4;
            float4 v = *(const float4*)(abase + (size_t)(c0 + cl) * HW + p4 * 4);
            *(float4*)&sX[cl][p4 * 4] = v;
        }
        {
            int ol = t >> 2, c4 = t & 3;
            float4 v = *(const float4*)(wbase + (size_t)ol * CCH + c0 + c4 * 4);
            sWt[c4 * 4 + 0][ol] = v.x;
            sWt[c4 * 4 + 1][ol] = v.y;
            sWt[c4 * 4 + 2][ol] = v.z;
            sWt[c4 * 4 + 3][ol] = v.w;
        }
        __syncthreads();
        #pragma unroll 4
        for (int cc = 0; cc < 16; cc++) {
            float4 xv  = *(const float4*)&sX[cc][ty * 4];
            float4 wv4 = *(const float4*)&sWt[cc][tx * 4];
            acc[0][0] += xv.x * wv4.x; acc[0][1] += xv.x * wv4.y;
            acc[0][2] += xv.x * wv4.z; acc[0][3] += xv.x * wv4.w;
            acc[1][0] += xv.y * wv4.x; acc[1][1] += xv.y * wv4.y;
            acc[1][2] += xv.y * wv4.z; acc[1][3] += xv.y * wv4.w;
            acc[2][0] += xv.z * wv4.x; acc[2][1] += xv.z * wv4.y;
            acc[2][2] += xv.z * wv4.z; acc[2][3] += xv.z * wv4.w;
            acc[3][0] += xv.w * wv4.x; acc[3][1] += xv.w * wv4.y;
            acc[3][2] += xv.w * wv4.z; acc[3][3] += xv.w * wv4.w;
        }
        __syncthreads();
    }

    #pragma unroll
    for (int i = 0; i < 4; i++)
        #pragma unroll
        for (int j = 0; j < 4; j++)
            sO[tx * 4 + j][ty * 4 + i] = acc[i][j];
    __syncthreads();

    const float* xres = x + ((size_t)b * CCH + ot * 64) * HW + h * 64;
    float* ob = out + ((size_t)b * CCH + ot * 64) * HW + h * 64;
    for (int idx = t; idx < 4096; idx += 256) {
        int ol = idx >> 6, pl = idx & 63;
        ob[(size_t)ol * HW + pl] =
            sO[ol][pl] + xres[(size_t)ol * HW + pl] + bo[ot * 64 + ol];
    }
}

// ---------------------------------------------------------------------------
extern "C" void kernel_launch(void* const* d_in, const int* in_sizes, int n_in,
                              void* d_out, int out_size) {
    (void)in_sizes; (void)n_in; (void)out_size;
    const float* x  = (const float*)d_in[0];
    const float* ns = (const float*)d_in[1];
    const float* nb = (const float*)d_in[2];
    const float* wq = (const float*)d_in[3];
    const float* bq = (const float*)d_in[4];
    const float* wk = (const float*)d_in[5];
    const float* bk = (const float*)d_in[6];
    const float* wv = (const float*)d_in[7];
    const float* bv = (const float*)d_in[8];
    const float* wo = (const float*)d_in[9];
    const float* bo = (const float*)d_in[10];
    float* out = (float*)d_out;

    gn_kernel<<<128, 256>>>(x, ns, nb);
    qkv_kernel<<<dim3(64, 8, 4), 256>>>(wq, bq, wk, bk, wv, bv);
    attn_kernel<<<dim3(16, 8, 16), 128>>>();
    oproj_kernel<<<dim3(64, 8, 4), 256>>>(x, wo, bo, out);
}

// round 3
// speedup vs baseline: 1.7859x; 1.6094x over previous
#include <cuda_runtime.h>

// ---------------------------------------------------------------------------
// MemoryEfficientAttnBlock: GroupNorm -> window QKV attention -> out proj + res
// B=4, C=512, H=W=64, WS=32 -> 16 windows of n=1024 tokens, 8 heads, d=64.
// fp32 SIMT, round 2: all inner loops restructured for LDS.128 / conflict-free
// shared access (R1 ncu: L1 pipe 85%, fma 43% -> shared-bound).
// ---------------------------------------------------------------------------

#define BB    4
#define CCH   512
#define HW    4096      // 64*64
#define NHEAD 8
#define DH    64
#define NWIN  16
#define NTOK  1024
#define CPG   16        // channels per group

// Scratch (device globals; allocation-free rule)
__device__ float g_hn[BB * CCH * HW];                 // group-normed x, [b][c][hw]
__device__ float g_q[NWIN * NHEAD * NTOK * DH];       // [win][head][n][d]
__device__ float g_k[NWIN * NHEAD * NTOK * DH];
__device__ float g_v[NWIN * NHEAD * NTOK * DH];
__device__ float g_ao[BB * CCH * HW];                 // attention output, [b][c][hw]

// ---------------------------------------------------------------------------
// Kernel 1: GroupNorm.  grid = 128 (b*32 groups), 256 threads.
// ---------------------------------------------------------------------------
__global__ __launch_bounds__(256) void gn_kernel(const float* __restrict__ x,
                                                 const float* __restrict__ scale,
                                                 const float* __restrict__ bias) {
    int b = blockIdx.x >> 5;
    int g = blockIdx.x & 31;
    const float4* xp = (const float4*)(x + (size_t)(b * CCH + g * CPG) * HW);
    float4* yp = (float4*)(g_hn + (size_t)(b * CCH + g * CPG) * HW);
    const int NV = CPG * HW / 4;  // 16384 float4s

    float s = 0.f, s2 = 0.f;
    for (int i = threadIdx.x; i < NV; i += 256) {
        float4 v = xp[i];
        s  += v.x + v.y + v.z + v.w;
        s2 += v.x * v.x + v.y * v.y + v.z * v.z + v.w * v.w;
    }
    __shared__ float rb[2][8];
    #pragma unroll
    for (int o = 16; o; o >>= 1) {
        s  += __shfl_xor_sync(0xffffffffu, s,  o);
        s2 += __shfl_xor_sync(0xffffffffu, s2, o);
    }
    int warp = threadIdx.x >> 5, lane = threadIdx.x & 31;
    if (lane == 0) { rb[0][warp] = s; rb[1][warp] = s2; }
    __syncthreads();
    if (warp == 0) {
        s  = (lane < 8) ? rb[0][lane] : 0.f;
        s2 = (lane < 8) ? rb[1][lane] : 0.f;
        #pragma unroll
        for (int o = 4; o; o >>= 1) {
            s  += __shfl_xor_sync(0xffffffffu, s,  o);
            s2 += __shfl_xor_sync(0xffffffffu, s2, o);
        }
        if (lane == 0) { rb[0][0] = s; rb[1][0] = s2; }
    }
    __syncthreads();
    const float n = (float)(CPG * HW);
    float mu  = rb[0][0] / n;
    float var = rb[1][0] / n - mu * mu;
    float rstd = rsqrtf(var + 1e-6f);

    for (int i = threadIdx.x; i < NV; i += 256) {
        int c = g * CPG + (i >> 10);
        float sc = scale[c] * rstd;
        float bi = bias[c] - mu * sc;
        float4 v = xp[i];
        v.x = v.x * sc + bi; v.y = v.y * sc + bi;
        v.z = v.z * sc + bi; v.w = v.w * sc + bi;
        yp[i] = v;
    }
}

// ---------------------------------------------------------------------------
// Kernel 2: fused QKV 1x1 conv.  grid = (64 h-rows, 8 heads, 4 b), 256 thr.
// Weight tiles stored TRANSPOSED in smem ([c][o]) so both operands of the
// micro-kernel are contiguous float4 LDS.128 (12 FFMA per LDS.128).
// ---------------------------------------------------------------------------
__global__ __launch_bounds__(256) void qkv_kernel(
    const float* __restrict__ wq, const float* __restrict__ bq,
    const float* __restrict__ wk, const float* __restrict__ bk,
    const float* __restrict__ wv, const float* __restrict__ bv) {
    __shared__ __align__(16) float sX[16][68];      // [c][pixel]
    __shared__ __align__(16) float sWt[3][16][68];  // [m][c][o]  (transposed)

    int h    = blockIdx.x;
    int head = blockIdx.y;
    int b    = blockIdx.z;
    int t  = threadIdx.x;
    int tx = t & 15, ty = t >> 4;   // tx -> o group, ty -> pixel group

    float acc[3][4][4];
    #pragma unroll
    for (int m = 0; m < 3; m++)
        #pragma unroll
        for (int i = 0; i < 4; i++)
            #pragma unroll
            for (int j = 0; j < 4; j++) acc[m][i][j] = 0.f;

    const float* xbase = g_hn + (size_t)b * CCH * HW + h * 64;
    const float* wbs[3] = { wq + (size_t)head * 64 * CCH,
                            wk + (size_t)head * 64 * CCH,
                            wv + (size_t)head * 64 * CCH };

    for (int cs = 0; cs < 32; cs++) {
        int c0 = cs * 16;
        {   // X tile [16 c][64 p] — one float4 per thread
            int p4 = t & 15, cl = t >> 4;
            float4 v = *(const float4*)(xbase + (size_t)(c0 + cl) * HW + p4 * 4);
            *(float4*)&sX[cl][p4 * 4] = v;
        }
        {   // W tiles, transposed into [c][o]
            int ol = t >> 2, c4 = t & 3;
            #pragma unroll
            for (int m = 0; m < 3; m++) {
                float4 v = *(const float4*)(wbs[m] + (size_t)ol * CCH + c0 + c4 * 4);
                sWt[m][c4 * 4 + 0][ol] = v.x;
                sWt[m][c4 * 4 + 1][ol] = v.y;
                sWt[m][c4 * 4 + 2][ol] = v.z;
                sWt[m][c4 * 4 + 3][ol] = v.w;
            }
        }
        __syncthreads();
        #pragma unroll 4
        for (int cc = 0; cc < 16; cc++) {
            float4 xv = *(const float4*)&sX[cc][ty * 4];   // broadcast per phase
            #pragma unroll
            for (int m = 0; m < 3; m++) {
                float4 wv4 = *(const float4*)&sWt[m][cc][tx * 4];  // conflict-free
                acc[m][0][0] += xv.x * wv4.x; acc[m][0][1] += xv.x * wv4.y;
                acc[m][0][2] += xv.x * wv4.z; acc[m][0][3] += xv.x * wv4.w;
                acc[m][1][0] += xv.y * wv4.x; acc[m][1][1] += xv.y * wv4.y;
                acc[m][1][2] += xv.y * wv4.z; acc[m][1][3] += xv.y * wv4.w;
                acc[m][2][0] += xv.z * wv4.x; acc[m][2][1] += xv.z * wv4.y;
                acc[m][2][2] += xv.z * wv4.z; acc[m][2][3] += xv.z * wv4.w;
                acc[m][3][0] += xv.w * wv4.x; acc[m][3][1] += xv.w * wv4.y;
                acc[m][3][2] += xv.w * wv4.z; acc[m][3][3] += xv.w * wv4.w;
            }
        }
        __syncthreads();
    }

    int wh = h >> 5, w1 = h & 31;
    float bq4[4], bk4[4], bv4[4];
    #pragma unroll
    for (int j = 0; j < 4; j++) {
        bq4[j] = bq[head * 64 + tx * 4 + j];
        bk4[j] = bk[head * 64 + tx * 4 + j];
        bv4[j] = bv[head * 64 + tx * 4 + j];
    }
    #pragma unroll
    for (int i = 0; i < 4; i++) {
        int w   = ty * 4 + i;
        int win = b * 4 + wh * 2 + (w >> 5);
        int nn  = w1 * 32 + (w & 31);
        size_t base = (((size_t)win * NHEAD + head) * NTOK + nn) * DH + tx * 4;
        float4 oq = { acc[0][i][0] + bq4[0], acc[0][i][1] + bq4[1],
                      acc[0][i][2] + bq4[2], acc[0][i][3] + bq4[3] };
        float4 ok = { acc[1][i][0] + bk4[0], acc[1][i][1] + bk4[1],
                      acc[1][i][2] + bk4[2], acc[1][i][3] + bk4[3] };
        float4 ov = { acc[2][i][0] + bv4[0], acc[2][i][1] + bv4[1],
                      acc[2][i][2] + bv4[2], acc[2][i][3] + bv4[3] };
        *(float4*)(g_q + base) = oq;
        *(float4*)(g_k + base) = ok;
        *(float4*)(g_v + base) = ov;
    }
}

// ---------------------------------------------------------------------------
// Kernel 3: windowed flash attention.
// grid = (16 q-tiles, 8 heads, 16 windows), 128 threads.
// q-tile 64 rows; 32 k-tiles of 32 rows, online softmax.
// Score cols per thread: cx + 8j  -> conflict-free K LDS.128.
// Out d-cols per thread: {cx*4..+3, 32+cx*4..+3} -> conflict-free V LDS.128.
// ---------------------------------------------------------------------------
__global__ __launch_bounds__(128) void attn_kernel() {
    __shared__ __align__(16) float sQ[64 * 68];   // Q, stride 68
    __shared__ __align__(16) float sKV[2 * 32 * 68]; // K then V; reused for output (stride 65)
    __shared__ __align__(16) float sP[64 * 36];   // P, stride 36

    float* sK = sKV;
    float* sV = sKV + 32 * 68;

    int qt   = blockIdx.x;
    int head = blockIdx.y;
    int win  = blockIdx.z;
    int t  = threadIdx.x;
    int cx = t & 7, ry = t >> 3;

    size_t hb = ((size_t)win * NHEAD + head) * NTOK * DH;

    // load Q tile (pre-scaled by 1/sqrt(64))
    for (int idx = t; idx < 1024; idx += 128) {   // 1024 float4
        int r = idx >> 4, d4 = idx & 15;
        float4 v = *(const float4*)(g_q + hb + (size_t)(qt * 64 + r) * DH + d4 * 4);
        v.x *= 0.125f; v.y *= 0.125f; v.z *= 0.125f; v.w *= 0.125f;
        *(float4*)&sQ[r * 68 + d4 * 4] = v;
    }

    float m[4], l[4], out[4][8];
    #pragma unroll
    for (int i = 0; i < 4; i++) {
        m[i] = -1e30f; l[i] = 0.f;
        #pragma unroll
        for (int j = 0; j < 8; j++) out[i][j] = 0.f;
    }

    for (int kt = 0; kt < 32; kt++) {
        // load K,V tiles (32 rows x 64 d)
        for (int idx = t; idx < 512; idx += 128) {
            int kc = idx >> 4, d4 = idx & 15;
            size_t gsrc = hb + (size_t)(kt * 32 + kc) * DH + d4 * 4;
            *(float4*)&sK[kc * 68 + d4 * 4] = *(const float4*)(g_k + gsrc);
            *(float4*)&sV[kc * 68 + d4 * 4] = *(const float4*)(g_v + gsrc);
        }
        __syncthreads();

        // scores: 4 q-rows x 4 k-cols (cols cx+8j) per thread, float4 over d
        float s[4][4];
        #pragma unroll
        for (int i = 0; i < 4; i++)
            #pragma unroll
            for (int j = 0; j < 4; j++) s[i][j] = 0.f;
        #pragma unroll 4
        for (int d4 = 0; d4 < 16; d4++) {
            float4 qv[4];
            #pragma unroll
            for (int i = 0; i < 4; i++)
                qv[i] = *(const float4*)&sQ[(ry * 4 + i) * 68 + d4 * 4];
            #pragma unroll
            for (int j = 0; j < 4; j++) {
                float4 kv = *(const float4*)&sK[(cx + 8 * j) * 68 + d4 * 4];
                #pragma unroll
                for (int i = 0; i < 4; i++)
                    s[i][j] += qv[i].x * kv.x + qv[i].y * kv.y
                             + qv[i].z * kv.z + qv[i].w * kv.w;
            }
        }

        // online softmax per row (8 lanes share a row)
        float alpha[4];
        #pragma unroll
        for (int i = 0; i < 4; i++) {
            float tm = fmaxf(fmaxf(s[i][0], s[i][1]), fmaxf(s[i][2], s[i][3]));
            tm = fmaxf(tm, __shfl_xor_sync(0xffffffffu, tm, 1));
            tm = fmaxf(tm, __shfl_xor_sync(0xffffffffu, tm, 2));
            tm = fmaxf(tm, __shfl_xor_sync(0xffffffffu, tm, 4));
            float mn = fmaxf(m[i], tm);
            float ps = 0.f;
            #pragma unroll
            for (int j = 0; j < 4; j++) {
                s[i][j] = __expf(s[i][j] - mn);
                ps += s[i][j];
            }
            ps += __shfl_xor_sync(0xffffffffu, ps, 1);
            ps += __shfl_xor_sync(0xffffffffu, ps, 2);
            ps += __shfl_xor_sync(0xffffffffu, ps, 4);
            float al = __expf(m[i] - mn);
            l[i] = l[i] * al + ps;
            m[i] = mn;
            alpha[i] = al;
        }

        // stage P (producer/consumer lanes are within one warp)
        __syncwarp();
        #pragma unroll
        for (int i = 0; i < 4; i++)
            #pragma unroll
            for (int j = 0; j < 4; j++)
                sP[(ry * 4 + i) * 36 + cx + 8 * j] = s[i][j];
        __syncwarp();

        // out += P @ V   (out d-cols: cx*4+{0..3} and 32+cx*4+{0..3})
        #pragma unroll
        for (int i = 0; i < 4; i++)
            #pragma unroll
            for (int j = 0; j < 8; j++) out[i][j] *= alpha[i];
        #pragma unroll 2
        for (int k4 = 0; k4 < 8; k4++) {
            float4 pv[4];
            #pragma unroll
            for (int i = 0; i < 4; i++)
                pv[i] = *(const float4*)&sP[(ry * 4 + i) * 36 + k4 * 4];
            #pragma unroll
            for (int kk = 0; kk < 4; kk++) {
                float4 va = *(const float4*)&sV[(k4 * 4 + kk) * 68 + cx * 4];
                float4 vb = *(const float4*)&sV[(k4 * 4 + kk) * 68 + 32 + cx * 4];
                #pragma unroll
                for (int i = 0; i < 4; i++) {
                    float p = (kk == 0) ? pv[i].x : (kk == 1) ? pv[i].y
                            : (kk == 2) ? pv[i].z : pv[i].w;
                    out[i][0] += p * va.x; out[i][1] += p * va.y;
                    out[i][2] += p * va.z; out[i][3] += p * va.w;
                    out[i][4] += p * vb.x; out[i][5] += p * vb.y;
                    out[i][6] += p * vb.z; out[i][7] += p * vb.w;
                }
            }
        }
        __syncthreads();   // before next tile overwrites sK/sV
    }

    // finalize; stage [row][d] with odd stride 65 into sKV for conflict-free
    // transposed readout
    float* sOut = sKV;
    #pragma unroll
    for (int i = 0; i < 4; i++) {
        float inv = 1.0f / l[i];
        int row = ry * 4 + i;
        #pragma unroll
        for (int j = 0; j < 4; j++) {
            sOut[row * 65 + cx * 4 + j]      = out[i][j]     * inv;
            sOut[row * 65 + 32 + cx * 4 + j] = out[i][j + 4] * inv;
        }
    }
    __syncthreads();

    int b  = win >> 2;
    int wh = (win >> 1) & 1;
    int ww = win & 1;
    for (int idx = t; idx < 4096; idx += 128) {
        int d = idx >> 6, r = idx & 63;
        int nn = qt * 64 + r;
        int h = wh * 32 + (nn >> 5);
        int w = ww * 32 + (nn & 31);
        g_ao[((size_t)b * CCH + head * 64 + d) * HW + h * 64 + w] = sOut[r * 65 + d];
    }
}

// ---------------------------------------------------------------------------
// Kernel 4: out projection + bias + residual.  grid = (64, 8, 4), 256 thr.
// Transposed weight tile in smem -> both operands LDS.128.
// ---------------------------------------------------------------------------
__global__ __launch_bounds__(256) void oproj_kernel(
    const float* __restrict__ x, const float* __restrict__ wo,
    const float* __restrict__ bo, float* __restrict__ out) {
    __shared__ __align__(16) float sX[16][68];
    __shared__ __align__(16) float sWt[16][68];   // [c][o] transposed
    __shared__ float sO[64][65];                  // [o][p] staging

    int h  = blockIdx.x;
    int ot = blockIdx.y;
    int b  = blockIdx.z;
    int t  = threadIdx.x;
    int tx = t & 15, ty = t >> 4;

    float acc[4][4];
    #pragma unroll
    for (int i = 0; i < 4; i++)
        #pragma unroll
        for (int j = 0; j < 4; j++) acc[i][j] = 0.f;

    const float* abase = g_ao + (size_t)b * CCH * HW + h * 64;
    const float* wbase = wo + (size_t)ot * 64 * CCH;

    for (int cs = 0; cs < 32; cs++) {
        int c0 = cs * 16;
        {
            int p4 = t & 15, cl = t >> 4;
            float4 v = *(const float4*)(abase + (size_t)(c0 + cl) * HW + p4 * 4);
            *(float4*)&sX[cl][p4 * 4] = v;
        }
        {
            int ol = t >> 2, c4 = t & 3;
            float4 v = *(const float4*)(wbase + (size_t)ol * CCH + c0 + c4 * 4);
            sWt[c4 * 4 + 0][ol] = v.x;
            sWt[c4 * 4 + 1][ol] = v.y;
            sWt[c4 * 4 + 2][ol] = v.z;
            sWt[c4 * 4 + 3][ol] = v.w;
        }
        __syncthreads();
        #pragma unroll 4
        for (int cc = 0; cc < 16; cc++) {
            float4 xv  = *(const float4*)&sX[cc][ty * 4];
            float4 wv4 = *(const float4*)&sWt[cc][tx * 4];
            acc[0][0] += xv.x * wv4.x; acc[0][1] += xv.x * wv4.y;
            acc[0][2] += xv.x * wv4.z; acc[0][3] += xv.x * wv4.w;
            acc[1][0] += xv.y * wv4.x; acc[1][1] += xv.y * wv4.y;
            acc[1][2] += xv.y * wv4.z; acc[1][3] += xv.y * wv4.w;
            acc[2][0] += xv.z * wv4.x; acc[2][1] += xv.z * wv4.y;
            acc[2][2] += xv.z * wv4.z; acc[2][3] += xv.z * wv4.w;
            acc[3][0] += xv.w * wv4.x; acc[3][1] += xv.w * wv4.y;
            acc[3][2] += xv.w * wv4.z; acc[3][3] += xv.w * wv4.w;
        }
        __syncthreads();
    }

    #pragma unroll
    for (int i = 0; i < 4; i++)
        #pragma unroll
        for (int j = 0; j < 4; j++)
            sO[tx * 4 + j][ty * 4 + i] = acc[i][j];
    __syncthreads();

    const float* xres = x + ((size_t)b * CCH + ot * 64) * HW + h * 64;
    float* ob = out + ((size_t)b * CCH + ot * 64) * HW + h * 64;
    for (int idx = t; idx < 4096; idx += 256) {
        int ol = idx >> 6, pl = idx & 63;
        ob[(size_t)ol * HW + pl] =
            sO[ol][pl] + xres[(size_t)ol * HW + pl] + bo[ot * 64 + ol];
    }
}

// ---------------------------------------------------------------------------
extern "C" void kernel_launch(void* const* d_in, const int* in_sizes, int n_in,
                              void* d_out, int out_size) {
    (void)in_sizes; (void)n_in; (void)out_size;
    const float* x  = (const float*)d_in[0];
    const float* ns = (const float*)d_in[1];
    const float* nb = (const float*)d_in[2];
    const float* wq = (const float*)d_in[3];
    const float* bq = (const float*)d_in[4];
    const float* wk = (const float*)d_in[5];
    const float* bk = (const float*)d_in[6];
    const float* wv = (const float*)d_in[7];
    const float* bv = (const float*)d_in[8];
    const float* wo = (const float*)d_in[9];
    const float* bo = (const float*)d_in[10];
    float* out = (float*)d_out;

    gn_kernel<<<128, 256>>>(x, ns, nb);
    qkv_kernel<<<dim3(64, 8, 4), 256>>>(wq, bq, wk, bk, wv, bv);
    attn_kernel<<<dim3(16, 8, 16), 128>>>();
    oproj_kernel<<<dim3(64, 8, 4), 256>>>(x, wo, bo, out);
}

// round 5
// speedup vs baseline: 2.5670x; 1.4374x over previous
#include <cuda_runtime.h>
#include <cstdint>

// ---------------------------------------------------------------------------
// MemoryEfficientAttnBlock on GB300 (sm_103a, compiled via compute_103)
// GroupNorm -> mma.sync(tf32) QKV proj -> SIMT window attention
//           -> mma.sync(tf32) out proj + bias + residual
// B=4, C=512, H=W=64, WS=32 -> 16 windows x 1024 tokens, 8 heads, d=64.
// tcgen05 is unavailable at this PTX target; mma.sync HMMA path instead.
// ---------------------------------------------------------------------------

#define BB    4
#define CCH   512
#define HW    4096
#define NHEAD 8
#define DH    64
#define NWIN  16
#define NTOK  1024
#define TT    (NWIN * NTOK)
#define CPG   16

__device__ float g_xnT[TT * CCH];                 // normed x, [token][c]
__device__ float g_q[NWIN * NHEAD * NTOK * DH];   // [win][head][n][d]
__device__ float g_k[NWIN * NHEAD * NTOK * DH];
__device__ float g_v[NWIN * NHEAD * NTOK * DH];
__device__ float g_aoT[TT * CCH];                 // attn out, [token][head*64+d]

// ---------------------------------------------------------------------------
// mma.sync helpers (portable PTX, runs on tensor pipe as HMMA)
// ---------------------------------------------------------------------------
__device__ __forceinline__ uint32_t f2tf32(float f) {
    uint32_t r;
    asm("cvt.rna.tf32.f32 %0, %1;" : "=r"(r) : "f"(f));
    return r;
}

// D(16x8) += A(16x8,row) * B(8x8,col);  tf32 inputs, f32 accum
__device__ __forceinline__ void mma_tf32(float* c, const uint32_t* a,
                                         const uint32_t* b) {
    asm volatile(
        "mma.sync.aligned.m16n8k8.row.col.f32.tf32.tf32.f32 "
        "{%0,%1,%2,%3}, {%4,%5,%6,%7}, {%8,%9}, {%0,%1,%2,%3};"
        : "+f"(c[0]), "+f"(c[1]), "+f"(c[2]), "+f"(c[3])
        : "r"(a[0]), "r"(a[1]), "r"(a[2]), "r"(a[3]), "r"(b[0]), "r"(b[1]));
}

// ---------------------------------------------------------------------------
// Kernel 1: GroupNorm -> token-major transpose.  grid = 128 (b,g), 256 thr.
// ---------------------------------------------------------------------------
__global__ __launch_bounds__(256) void gn_kernel(const float* __restrict__ x,
                                                 const float* __restrict__ scale,
                                                 const float* __restrict__ bias) {
    __shared__ float rb[2][8];
    __shared__ __align__(16) float sS[16][68];

    int b = blockIdx.x >> 5;
    int g = blockIdx.x & 31;
    int c0 = g * CPG;
    int t = threadIdx.x;
    const float4* xp = (const float4*)(x + (size_t)(b * CCH + c0) * HW);
    const int NV = CPG * HW / 4;

    float s = 0.f, s2 = 0.f;
    for (int i = t; i < NV; i += 256) {
        float4 v = xp[i];
        s  += v.x + v.y + v.z + v.w;
        s2 += v.x * v.x + v.y * v.y + v.z * v.z + v.w * v.w;
    }
    #pragma unroll
    for (int o = 16; o; o >>= 1) {
        s  += __shfl_xor_sync(0xffffffffu, s,  o);
        s2 += __shfl_xor_sync(0xffffffffu, s2, o);
    }
    int warp = t >> 5, lane = t & 31;
    if (lane == 0) { rb[0][warp] = s; rb[1][warp] = s2; }
    __syncthreads();
    if (warp == 0) {
        s  = (lane < 8) ? rb[0][lane] : 0.f;
        s2 = (lane < 8) ? rb[1][lane] : 0.f;
        #pragma unroll
        for (int o = 4; o; o >>= 1) {
            s  += __shfl_xor_sync(0xffffffffu, s,  o);
            s2 += __shfl_xor_sync(0xffffffffu, s2, o);
        }
        if (lane == 0) { rb[0][0] = s; rb[1][0] = s2; }
    }
    __syncthreads();
    const float n = (float)(CPG * HW);
    float mu  = rb[0][0] / n;
    float var = rb[1][0] / n - mu * mu;
    float rstd = rsqrtf(var + 1e-6f);

    int cl = t >> 4, w4 = t & 15;       // tile-load role
    float sc = scale[c0 + cl] * rstd;
    float bi = bias[c0 + cl] - mu * sc;
    int tok = t >> 2, c4 = t & 3;       // write role

    for (int h = 0; h < 64; h++) {
        float4 v = *(const float4*)(x + (size_t)(b * CCH + c0 + cl) * HW + h * 64 + w4 * 4);
        v.x = v.x * sc + bi; v.y = v.y * sc + bi;
        v.z = v.z * sc + bi; v.w = v.w * sc + bi;
        *(float4*)&sS[cl][w4 * 4] = v;
        __syncthreads();
        int win = b * 4 + (h >> 5) * 2 + (tok >> 5);
        int nn  = (h & 31) * 32 + (tok & 31);
        float4 o4 = { sS[c4 * 4 + 0][tok], sS[c4 * 4 + 1][tok],
                      sS[c4 * 4 + 2][tok], sS[c4 * 4 + 3][tok] };
        *(float4*)(g_xnT + (size_t)(win * NTOK + nn) * CCH + c0 + c4 * 4) = o4;
        __syncthreads();
    }
}

// ---------------------------------------------------------------------------
// Kernel 2: QKV GEMM on mma.sync tf32.
// grid = (128 n-tiles, 12 m-tiles), 256 threads (8 warps: 2 m-rows x 4 n-cols).
// CTA tile D[128 o][128 tok], K=512 in 16 chunks of 32.
// smem tiles row-stride 36 words -> all fragment LDS conflict-free.
// ---------------------------------------------------------------------------
__global__ __launch_bounds__(256) void qkv_mma_kernel(
    const float* __restrict__ wq, const float* __restrict__ bq,
    const float* __restrict__ wk, const float* __restrict__ bk,
    const float* __restrict__ wv, const float* __restrict__ bv) {
    __shared__ __align__(16) float sA[128 * 36];   // W tile [o][k]; reused as sT
    __shared__ __align__(16) float sB[128 * 36];   // X tile [n][k]

    int t = threadIdx.x, lane = t & 31, wid = t >> 5;
    int wrow = wid & 1, wcol = wid >> 1;           // 2 x 4 warp grid
    int nt = blockIdx.x, mt = blockIdx.y;

    const float* W    = (mt < 4 ? wq : mt < 8 ? wk : wv) + (size_t)(mt & 3) * 128 * CCH;
    const float* BIAS = (mt < 4 ? bq : mt < 8 ? bk : bv);
    float* OUT        = (mt < 4 ? g_q : mt < 8 ? g_k : g_v);
    int win = nt >> 3;
    int n0  = (nt & 7) * 128;
    const float* X = g_xnT + (size_t)(win * NTOK + n0) * CCH;

    float acc[4][4][4];
    #pragma unroll
    for (int i = 0; i < 4; i++)
        #pragma unroll
        for (int j = 0; j < 4; j++)
            #pragma unroll
            for (int r = 0; r < 4; r++) acc[i][j][r] = 0.f;

    int lrow = t >> 3, lc4 = t & 7;   // gmem->smem load role
    int lq = lane >> 2, lr = lane & 3;

    for (int chunk = 0; chunk < 16; chunk++) {
        int c0 = chunk * 32;
        #pragma unroll
        for (int i = 0; i < 4; i++) {
            int row = lrow + i * 32;
            float4 a = *(const float4*)(W + (size_t)row * CCH + c0 + lc4 * 4);
            float4 b = *(const float4*)(X + (size_t)row * CCH + c0 + lc4 * 4);
            uint32_t* pa = (uint32_t*)&sA[row * 36 + lc4 * 4];
            uint32_t* pb = (uint32_t*)&sB[row * 36 + lc4 * 4];
            pa[0] = f2tf32(a.x); pa[1] = f2tf32(a.y);
            pa[2] = f2tf32(a.z); pa[3] = f2tf32(a.w);
            pb[0] = f2tf32(b.x); pb[1] = f2tf32(b.y);
            pb[2] = f2tf32(b.z); pb[3] = f2tf32(b.w);
        }
        __syncthreads();
        #pragma unroll
        for (int ks = 0; ks < 4; ks++) {
            int k0 = ks * 8;
            uint32_t af[4][4], bf[4][2];
            #pragma unroll
            for (int mi = 0; mi < 4; mi++) {
                int m = wrow * 64 + mi * 16 + lq;
                af[mi][0] = __float_as_uint(sA[m * 36 + k0 + lr]);
                af[mi][1] = __float_as_uint(sA[(m + 8) * 36 + k0 + lr]);
                af[mi][2] = __float_as_uint(sA[m * 36 + k0 + lr + 4]);
                af[mi][3] = __float_as_uint(sA[(m + 8) * 36 + k0 + lr + 4]);
            }
            #pragma unroll
            for (int ni = 0; ni < 4; ni++) {
                int nn = wcol * 32 + ni * 8 + lq;
                bf[ni][0] = __float_as_uint(sB[nn * 36 + k0 + lr]);
                bf[ni][1] = __float_as_uint(sB[nn * 36 + k0 + lr + 4]);
            }
            #pragma unroll
            for (int mi = 0; mi < 4; mi++)
                #pragma unroll
                for (int ni = 0; ni < 4; ni++)
                    mma_tf32(acc[mi][ni], af[mi], bf[ni]);
        }
        __syncthreads();
    }

    // epilogue: per 32-token chunk, stage [n][o] in sA region, coalesced write
    float* sT = sA;   // [32 n][132 o-stride]
    int o0c = (mt & 3) * 128;
    for (int cb = 0; cb < 4; cb++) {
        if (wcol == cb) {
            #pragma unroll
            for (int mi = 0; mi < 4; mi++) {
                int ob = wrow * 64 + mi * 16 + lq;
                #pragma unroll
                for (int ni = 0; ni < 4; ni++) {
                    int nb = ni * 8 + 2 * lr;
                    sT[nb * 132 + ob]           = acc[mi][ni][0];
                    sT[(nb + 1) * 132 + ob]     = acc[mi][ni][1];
                    sT[nb * 132 + ob + 8]       = acc[mi][ni][2];
                    sT[(nb + 1) * 132 + ob + 8] = acc[mi][ni][3];
                }
            }
        }
        __syncthreads();
        for (int idx = t; idx < 1024; idx += 256) {   // 32 n x 32 float4
            int nn = idx >> 5, of4 = (idx & 31) * 4;
            int ochan = o0c + of4;
            int head = ochan >> 6, d = ochan & 63;
            float4 v = *(const float4*)&sT[nn * 132 + of4];
            float4 bb = *(const float4*)&BIAS[ochan];
            v.x += bb.x; v.y += bb.y; v.z += bb.z; v.w += bb.w;
            size_t ga = ((size_t)(win * NHEAD + head) * NTOK + n0 + cb * 32 + nn) * DH + d;
            *(float4*)(OUT + ga) = v;
        }
        __syncthreads();
    }
}

// ---------------------------------------------------------------------------
// Kernel 3: windowed flash attention (SIMT fp32, validated core).
// grid = (16 q-tiles, 8 heads, 16 windows), 128 threads.
// Epilogue writes token-major g_aoT[token][head*64+d].
// ---------------------------------------------------------------------------
__global__ __launch_bounds__(128) void attn_kernel() {
    __shared__ __align__(16) float sQ[64 * 68];
    __shared__ __align__(16) float sKV[2 * 32 * 68];
    __shared__ __align__(16) float sP[64 * 36];

    float* sK = sKV;
    float* sV = sKV + 32 * 68;

    int qt   = blockIdx.x;
    int head = blockIdx.y;
    int win  = blockIdx.z;
    int t  = threadIdx.x;
    int cx = t & 7, ry = t >> 3;

    size_t hb = ((size_t)win * NHEAD + head) * NTOK * DH;

    for (int idx = t; idx < 1024; idx += 128) {
        int r = idx >> 4, d4 = idx & 15;
        float4 v = *(const float4*)(g_q + hb + (size_t)(qt * 64 + r) * DH + d4 * 4);
        v.x *= 0.125f; v.y *= 0.125f; v.z *= 0.125f; v.w *= 0.125f;
        *(float4*)&sQ[r * 68 + d4 * 4] = v;
    }

    float m[4], l[4], out[4][8];
    #pragma unroll
    for (int i = 0; i < 4; i++) {
        m[i] = -1e30f; l[i] = 0.f;
        #pragma unroll
        for (int j = 0; j < 8; j++) out[i][j] = 0.f;
    }

    for (int kt = 0; kt < 32; kt++) {
        for (int idx = t; idx < 512; idx += 128) {
            int kc = idx >> 4, d4 = idx & 15;
            size_t gsrc = hb + (size_t)(kt * 32 + kc) * DH + d4 * 4;
            *(float4*)&sK[kc * 68 + d4 * 4] = *(const float4*)(g_k + gsrc);
            *(float4*)&sV[kc * 68 + d4 * 4] = *(const float4*)(g_v + gsrc);
        }
        __syncthreads();

        float s[4][4];
        #pragma unroll
        for (int i = 0; i < 4; i++)
            #pragma unroll
            for (int j = 0; j < 4; j++) s[i][j] = 0.f;
        #pragma unroll 4
        for (int d4 = 0; d4 < 16; d4++) {
            float4 qv[4];
            #pragma unroll
            for (int i = 0; i < 4; i++)
                qv[i] = *(const float4*)&sQ[(ry * 4 + i) * 68 + d4 * 4];
            #pragma unroll
            for (int j = 0; j < 4; j++) {
                float4 kv = *(const float4*)&sK[(cx + 8 * j) * 68 + d4 * 4];
                #pragma unroll
                for (int i = 0; i < 4; i++)
                    s[i][j] += qv[i].x * kv.x + qv[i].y * kv.y
                             + qv[i].z * kv.z + qv[i].w * kv.w;
            }
        }

        float alpha[4];
        #pragma unroll
        for (int i = 0; i < 4; i++) {
            float tm = fmaxf(fmaxf(s[i][0], s[i][1]), fmaxf(s[i][2], s[i][3]));
            tm = fmaxf(tm, __shfl_xor_sync(0xffffffffu, tm, 1));
            tm = fmaxf(tm, __shfl_xor_sync(0xffffffffu, tm, 2));
            tm = fmaxf(tm, __shfl_xor_sync(0xffffffffu, tm, 4));
            float mn = fmaxf(m[i], tm);
            float ps = 0.f;
            #pragma unroll
            for (int j = 0; j < 4; j++) {
                s[i][j] = __expf(s[i][j] - mn);
                ps += s[i][j];
            }
            ps += __shfl_xor_sync(0xffffffffu, ps, 1);
            ps += __shfl_xor_sync(0xffffffffu, ps, 2);
            ps += __shfl_xor_sync(0xffffffffu, ps, 4);
            float al = __expf(m[i] - mn);
            l[i] = l[i] * al + ps;
            m[i] = mn;
            alpha[i] = al;
        }

        __syncwarp();
        #pragma unroll
        for (int i = 0; i < 4; i++)
            #pragma unroll
            for (int j = 0; j < 4; j++)
                sP[(ry * 4 + i) * 36 + cx + 8 * j] = s[i][j];
        __syncwarp();

        #pragma unroll
        for (int i = 0; i < 4; i++)
            #pragma unroll
            for (int j = 0; j < 8; j++) out[i][j] *= alpha[i];
        #pragma unroll 2
        for (int k4 = 0; k4 < 8; k4++) {
            float4 pv[4];
            #pragma unroll
            for (int i = 0; i < 4; i++)
                pv[i] = *(const float4*)&sP[(ry * 4 + i) * 36 + k4 * 4];
            #pragma unroll
            for (int kk = 0; kk < 4; kk++) {
                float4 va = *(const float4*)&sV[(k4 * 4 + kk) * 68 + cx * 4];
                float4 vb = *(const float4*)&sV[(k4 * 4 + kk) * 68 + 32 + cx * 4];
                #pragma unroll
                for (int i = 0; i < 4; i++) {
                    float p = (kk == 0) ? pv[i].x : (kk == 1) ? pv[i].y
                            : (kk == 2) ? pv[i].z : pv[i].w;
                    out[i][0] += p * va.x; out[i][1] += p * va.y;
                    out[i][2] += p * va.z; out[i][3] += p * va.w;
                    out[i][4] += p * vb.x; out[i][5] += p * vb.y;
                    out[i][6] += p * vb.z; out[i][7] += p * vb.w;
                }
            }
        }
        __syncthreads();
    }

    float* sOut = sKV;
    #pragma unroll
    for (int i = 0; i < 4; i++) {
        float inv = 1.0f / l[i];
        int row = ry * 4 + i;
        #pragma unroll
        for (int j = 0; j < 4; j++) {
            sOut[row * 65 + cx * 4 + j]      = out[i][j]     * inv;
            sOut[row * 65 + 32 + cx * 4 + j] = out[i][j + 4] * inv;
        }
    }
    __syncthreads();

    size_t tb = ((size_t)win * NTOK + qt * 64) * CCH + head * DH;
    for (int idx = t; idx < 4096; idx += 128) {
        int r = idx >> 6, d = idx & 63;
        g_aoT[tb + (size_t)r * CCH + d] = sOut[r * 65 + d];
    }
}

// ---------------------------------------------------------------------------
// Kernel 4: out projection on mma.sync tf32 + bias + residual.
// grid = (128 n-tiles, 4 m-tiles), 256 threads.
// ---------------------------------------------------------------------------
__global__ __launch_bounds__(256) void oproj_mma_kernel(
    const float* __restrict__ x, const float* __restrict__ wo,
    const float* __restrict__ bo, float* __restrict__ out) {
    __shared__ __align__(16) float sA[128 * 36];   // W tile; reused as sT [o][36]
    __shared__ __align__(16) float sB[128 * 36];   // X tile

    int t = threadIdx.x, lane = t & 31, wid = t >> 5;
    int wrow = wid & 1, wcol = wid >> 1;
    int nt = blockIdx.x, mt = blockIdx.y;

    int o0  = mt * 128;
    int win = nt >> 3;
    int n0  = (nt & 7) * 128;
    int b   = win >> 2, wh = (win >> 1) & 1, ww = win & 1;
    const float* W = wo + (size_t)o0 * CCH;
    const float* X = g_aoT + (size_t)(win * NTOK + n0) * CCH;

    float acc[4][4][4];
    #pragma unroll
    for (int i = 0; i < 4; i++)
        #pragma unroll
        for (int j = 0; j < 4; j++)
            #pragma unroll
            for (int r = 0; r < 4; r++) acc[i][j][r] = 0.f;

    int lrow = t >> 3, lc4 = t & 7;
    int lq = lane >> 2, lr = lane & 3;

    for (int chunk = 0; chunk < 16; chunk++) {
        int c0 = chunk * 32;
        #pragma unroll
        for (int i = 0; i < 4; i++) {
            int row = lrow + i * 32;
            float4 a = *(const float4*)(W + (size_t)row * CCH + c0 + lc4 * 4);
            float4 bv = *(const float4*)(X + (size_t)row * CCH + c0 + lc4 * 4);
            uint32_t* pa = (uint32_t*)&sA[row * 36 + lc4 * 4];
            uint32_t* pb = (uint32_t*)&sB[row * 36 + lc4 * 4];
            pa[0] = f2tf32(a.x);  pa[1] = f2tf32(a.y);
            pa[2] = f2tf32(a.z);  pa[3] = f2tf32(a.w);
            pb[0] = f2tf32(bv.x); pb[1] = f2tf32(bv.y);
            pb[2] = f2tf32(bv.z); pb[3] = f2tf32(bv.w);
        }
        __syncthreads();
        #pragma unroll
        for (int ks = 0; ks < 4; ks++) {
            int k0 = ks * 8;
            uint32_t af[4][4], bf[4][2];
            #pragma unroll
            for (int mi = 0; mi < 4; mi++) {
                int m = wrow * 64 + mi * 16 + lq;
                af[mi][0] = __float_as_uint(sA[m * 36 + k0 + lr]);
                af[mi][1] = __float_as_uint(sA[(m + 8) * 36 + k0 + lr]);
                af[mi][2] = __float_as_uint(sA[m * 36 + k0 + lr + 4]);
                af[mi][3] = __float_as_uint(sA[(m + 8) * 36 + k0 + lr + 4]);
            }
            #pragma unroll
            for (int ni = 0; ni < 4; ni++) {
                int nn = wcol * 32 + ni * 8 + lq;
                bf[ni][0] = __float_as_uint(sB[nn * 36 + k0 + lr]);
                bf[ni][1] = __float_as_uint(sB[nn * 36 + k0 + lr + 4]);
            }
            #pragma unroll
            for (int mi = 0; mi < 4; mi++)
                #pragma unroll
                for (int ni = 0; ni < 4; ni++)
                    mma_tf32(acc[mi][ni], af[mi], bf[ni]);
        }
        __syncthreads();
    }

    // epilogue: per 32-token chunk stage sT[128 o][36], add bias+residual
    float* sT = sA;
    for (int cb = 0; cb < 4; cb++) {
        if (wcol == cb) {
            #pragma unroll
            for (int mi = 0; mi < 4; mi++) {
                int ob = wrow * 64 + mi * 16 + lq;
                #pragma unroll
                for (int ni = 0; ni < 4; ni++) {
                    int nb = ni * 8 + 2 * lr;
                    sT[ob * 36 + nb]           = acc[mi][ni][0];
                    sT[ob * 36 + nb + 1]       = acc[mi][ni][1];
                    sT[(ob + 8) * 36 + nb]     = acc[mi][ni][2];
                    sT[(ob + 8) * 36 + nb + 1] = acc[mi][ni][3];
                }
            }
        }
        __syncthreads();

        int nb = n0 + cb * 32;
        int w1 = nb >> 5;
        int h  = wh * 32 + (w1 & 31);
        for (int idx = t; idx < 1024; idx += 256) {   // 128 o x 8 float4
            int o = idx >> 3, f4 = idx & 7;
            float4 v = *(const float4*)&sT[o * 36 + f4 * 4];
            float bval = bo[o0 + o];
            size_t ga = ((size_t)(b * CCH + o0 + o) * HW) + h * 64 + ww * 32 + f4 * 4;
            float4 xr = *(const float4*)(x + ga);
            v.x += bval + xr.x; v.y += bval + xr.y;
            v.z += bval + xr.z; v.w += bval + xr.w;
            *(float4*)(out + ga) = v;
        }
        __syncthreads();
    }
}

// ---------------------------------------------------------------------------
extern "C" void kernel_launch(void* const* d_in, const int* in_sizes, int n_in,
                              void* d_out, int out_size) {
    (void)in_sizes; (void)n_in; (void)out_size;
    const float* x  = (const float*)d_in[0];
    const float* ns = (const float*)d_in[1];
    const float* nb = (const float*)d_in[2];
    const float* wq = (const float*)d_in[3];
    const float* bq = (const float*)d_in[4];
    const float* wk = (const float*)d_in[5];
    const float* bk = (const float*)d_in[6];
    const float* wv = (const float*)d_in[7];
    const float* bv = (const float*)d_in[8];
    const float* wo = (const float*)d_in[9];
    const float* bo = (const float*)d_in[10];
    float* out = (float*)d_out;

    gn_kernel<<<128, 256>>>(x, ns, nb);
    qkv_mma_kernel<<<dim3(128, 12), 256>>>(wq, bq, wk, bk, wv, bv);
    attn_kernel<<<dim3(16, 8, 16), 128>>>();
    oproj_mma_kernel<<<dim3(128, 4), 256>>>(x, wo, bo, out);
}

// round 6
// speedup vs baseline: 5.0516x; 1.9679x over previous
#include <cuda_runtime.h>
#include <cstdint>

// ---------------------------------------------------------------------------
// MemoryEfficientAttnBlock on GB300 (sm_103a via compute_103)
// GroupNorm -> mma.sync(tf32) QKV -> mma.sync(tf32) flash attention
//           -> mma.sync(tf32) out proj + bias + residual
// ---------------------------------------------------------------------------

#define BB    4
#define CCH   512
#define HW    4096
#define NHEAD 8
#define DH    64
#define NWIN  16
#define NTOK  1024
#define TT    (NWIN * NTOK)
#define CPG   16

__device__ float g_xnT[TT * CCH];                 // normed x, [token][c]
__device__ float g_q[NWIN * NHEAD * NTOK * DH];   // [win][head][n][d]
__device__ float g_k[NWIN * NHEAD * NTOK * DH];
__device__ float g_v[NWIN * NHEAD * NTOK * DH];
__device__ float g_aoT[TT * CCH];                 // attn out, [token][head*64+d]

__device__ __forceinline__ uint32_t f2tf32(float f) {
    uint32_t r;
    asm("cvt.rna.tf32.f32 %0, %1;" : "=r"(r) : "f"(f));
    return r;
}

// D(16x8) += A(16x8,row) * B(8x8,col); tf32 in, f32 accum
__device__ __forceinline__ void mma_tf32(float* c, const uint32_t* a,
                                         const uint32_t* b) {
    asm volatile(
        "mma.sync.aligned.m16n8k8.row.col.f32.tf32.tf32.f32 "
        "{%0,%1,%2,%3}, {%4,%5,%6,%7}, {%8,%9}, {%0,%1,%2,%3};"
        : "+f"(c[0]), "+f"(c[1]), "+f"(c[2]), "+f"(c[3])
        : "r"(a[0]), "r"(a[1]), "r"(a[2]), "r"(a[3]), "r"(b[0]), "r"(b[1]));
}

// ---------------------------------------------------------------------------
// Kernel 1: GroupNorm -> token-major transpose.  grid = 128 (b,g), 256 thr.
// ---------------------------------------------------------------------------
__global__ __launch_bounds__(256) void gn_kernel(const float* __restrict__ x,
                                                 const float* __restrict__ scale,
                                                 const float* __restrict__ bias) {
    __shared__ float rb[2][8];
    __shared__ __align__(16) float sS[16][68];

    int b = blockIdx.x >> 5;
    int g = blockIdx.x & 31;
    int c0 = g * CPG;
    int t = threadIdx.x;
    const float4* xp = (const float4*)(x + (size_t)(b * CCH + c0) * HW);
    const int NV = CPG * HW / 4;

    float s = 0.f, s2 = 0.f;
    for (int i = t; i < NV; i += 256) {
        float4 v = xp[i];
        s  += v.x + v.y + v.z + v.w;
        s2 += v.x * v.x + v.y * v.y + v.z * v.z + v.w * v.w;
    }
    #pragma unroll
    for (int o = 16; o; o >>= 1) {
        s  += __shfl_xor_sync(0xffffffffu, s,  o);
        s2 += __shfl_xor_sync(0xffffffffu, s2, o);
    }
    int warp = t >> 5, lane = t & 31;
    if (lane == 0) { rb[0][warp] = s; rb[1][warp] = s2; }
    __syncthreads();
    if (warp == 0) {
        s  = (lane < 8) ? rb[0][lane] : 0.f;
        s2 = (lane < 8) ? rb[1][lane] : 0.f;
        #pragma unroll
        for (int o = 4; o; o >>= 1) {
            s  += __shfl_xor_sync(0xffffffffu, s,  o);
            s2 += __shfl_xor_sync(0xffffffffu, s2, o);
        }
        if (lane == 0) { rb[0][0] = s; rb[1][0] = s2; }
    }
    __syncthreads();
    const float n = (float)(CPG * HW);
    float mu  = rb[0][0] / n;
    float var = rb[1][0] / n - mu * mu;
    float rstd = rsqrtf(var + 1e-6f);

    int cl = t >> 4, w4 = t & 15;
    float sc = scale[c0 + cl] * rstd;
    float bi = bias[c0 + cl] - mu * sc;
    int tok = t >> 2, c4 = t & 3;

    for (int h = 0; h < 64; h++) {
        float4 v = *(const float4*)(x + (size_t)(b * CCH + c0 + cl) * HW + h * 64 + w4 * 4);
        v.x = v.x * sc + bi; v.y = v.y * sc + bi;
        v.z = v.z * sc + bi; v.w = v.w * sc + bi;
        *(float4*)&sS[cl][w4 * 4] = v;
        __syncthreads();
        int win = b * 4 + (h >> 5) * 2 + (tok >> 5);
        int nn  = (h & 31) * 32 + (tok & 31);
        float4 o4 = { sS[c4 * 4 + 0][tok], sS[c4 * 4 + 1][tok],
                      sS[c4 * 4 + 2][tok], sS[c4 * 4 + 3][tok] };
        *(float4*)(g_xnT + (size_t)(win * NTOK + nn) * CCH + c0 + c4 * 4) = o4;
        __syncthreads();
    }
}

// ---------------------------------------------------------------------------
// Kernel 2: QKV GEMM, mma.sync tf32, register-prefetch pipelined.
// grid = (128 n-tiles, 12 m-tiles), 256 threads (2x4 warps).
// ---------------------------------------------------------------------------
__global__ __launch_bounds__(256) void qkv_mma_kernel(
    const float* __restrict__ wq, const float* __restrict__ bq,
    const float* __restrict__ wk, const float* __restrict__ bk,
    const float* __restrict__ wv, const float* __restrict__ bv) {
    __shared__ __align__(16) float sA[128 * 36];
    __shared__ __align__(16) float sB[128 * 36];

    int t = threadIdx.x, lane = t & 31, wid = t >> 5;
    int wrow = wid & 1, wcol = wid >> 1;
    int nt = blockIdx.x, mt = blockIdx.y;

    const float* W    = (mt < 4 ? wq : mt < 8 ? wk : wv) + (size_t)(mt & 3) * 128 * CCH;
    const float* BIAS = (mt < 4 ? bq : mt < 8 ? bk : bv);
    float* OUT        = (mt < 4 ? g_q : mt < 8 ? g_k : g_v);
    int win = nt >> 3;
    int n0  = (nt & 7) * 128;
    const float* X = g_xnT + (size_t)(win * NTOK + n0) * CCH;

    float acc[4][4][4];
    #pragma unroll
    for (int i = 0; i < 4; i++)
        #pragma unroll
        for (int j = 0; j < 4; j++)
            #pragma unroll
            for (int r = 0; r < 4; r++) acc[i][j][r] = 0.f;

    int lrow = t >> 3, lc4 = t & 7;
    int lq = lane >> 2, lr = lane & 3;

    float4 pa4[4], pb4[4];
    #pragma unroll
    for (int i = 0; i < 4; i++) {
        int row = lrow + i * 32;
        pa4[i] = *(const float4*)(W + (size_t)row * CCH + lc4 * 4);
        pb4[i] = *(const float4*)(X + (size_t)row * CCH + lc4 * 4);
    }

    for (int chunk = 0; chunk < 16; chunk++) {
        #pragma unroll
        for (int i = 0; i < 4; i++) {
            int row = lrow + i * 32;
            uint32_t* pa = (uint32_t*)&sA[row * 36 + lc4 * 4];
            uint32_t* pb = (uint32_t*)&sB[row * 36 + lc4 * 4];
            pa[0] = f2tf32(pa4[i].x); pa[1] = f2tf32(pa4[i].y);
            pa[2] = f2tf32(pa4[i].z); pa[3] = f2tf32(pa4[i].w);
            pb[0] = f2tf32(pb4[i].x); pb[1] = f2tf32(pb4[i].y);
            pb[2] = f2tf32(pb4[i].z); pb[3] = f2tf32(pb4[i].w);
        }
        if (chunk < 15) {
            int c0n = (chunk + 1) * 32;
            #pragma unroll
            for (int i = 0; i < 4; i++) {
                int row = lrow + i * 32;
                pa4[i] = *(const float4*)(W + (size_t)row * CCH + c0n + lc4 * 4);
                pb4[i] = *(const float4*)(X + (size_t)row * CCH + c0n + lc4 * 4);
            }
        }
        __syncthreads();
        #pragma unroll
        for (int ks = 0; ks < 4; ks++) {
            int k0 = ks * 8;
            uint32_t af[4][4], bf[4][2];
            #pragma unroll
            for (int mi = 0; mi < 4; mi++) {
                int m = wrow * 64 + mi * 16 + lq;
                af[mi][0] = __float_as_uint(sA[m * 36 + k0 + lr]);
                af[mi][1] = __float_as_uint(sA[(m + 8) * 36 + k0 + lr]);
                af[mi][2] = __float_as_uint(sA[m * 36 + k0 + lr + 4]);
                af[mi][3] = __float_as_uint(sA[(m + 8) * 36 + k0 + lr + 4]);
            }
            #pragma unroll
            for (int ni = 0; ni < 4; ni++) {
                int nn = wcol * 32 + ni * 8 + lq;
                bf[ni][0] = __float_as_uint(sB[nn * 36 + k0 + lr]);
                bf[ni][1] = __float_as_uint(sB[nn * 36 + k0 + lr + 4]);
            }
            #pragma unroll
            for (int mi = 0; mi < 4; mi++)
                #pragma unroll
                for (int ni = 0; ni < 4; ni++)
                    mma_tf32(acc[mi][ni], af[mi], bf[ni]);
        }
        __syncthreads();
    }

    float* sT = sA;   // [32 n][132 o]
    int o0c = (mt & 3) * 128;
    for (int cb = 0; cb < 4; cb++) {
        if (wcol == cb) {
            #pragma unroll
            for (int mi = 0; mi < 4; mi++) {
                int ob = wrow * 64 + mi * 16 + lq;
                #pragma unroll
                for (int ni = 0; ni < 4; ni++) {
                    int nb = ni * 8 + 2 * lr;
                    sT[nb * 132 + ob]           = acc[mi][ni][0];
                    sT[(nb + 1) * 132 + ob]     = acc[mi][ni][1];
                    sT[nb * 132 + ob + 8]       = acc[mi][ni][2];
                    sT[(nb + 1) * 132 + ob + 8] = acc[mi][ni][3];
                }
            }
        }
        __syncthreads();
        for (int idx = t; idx < 1024; idx += 256) {
            int nn = idx >> 5, of4 = (idx & 31) * 4;
            int ochan = o0c + of4;
            int head = ochan >> 6, d = ochan & 63;
            float4 v = *(const float4*)&sT[nn * 132 + of4];
            float4 bb = *(const float4*)&BIAS[ochan];
            v.x += bb.x; v.y += bb.y; v.z += bb.z; v.w += bb.w;
            size_t ga = ((size_t)(win * NHEAD + head) * NTOK + n0 + cb * 32 + nn) * DH + d;
            *(float4*)(OUT + ga) = v;
        }
        __syncthreads();
    }
}

// ---------------------------------------------------------------------------
// Kernel 3: flash attention on mma.sync tf32.
// grid = (16 q-tiles, 8 heads, 16 windows), 128 threads (4 warps x 16 q-rows).
// Q persistent in A-fragments; K/V tiles (64 rows) in smem as tf32 bits.
// P stays in registers (quad-shuffle C->A fragment transform).
// ---------------------------------------------------------------------------
__global__ __launch_bounds__(128) void attn_mma_kernel() {
    __shared__ __align__(16) float sK[64 * 72];
    __shared__ __align__(16) float sV[64 * 72];

    int qt = blockIdx.x, head = blockIdx.y, win = blockIdx.z;
    int t = threadIdx.x, lane = t & 31, wid = t >> 5;
    int lq = lane >> 2, lr = lane & 3;
    int q0w = wid * 16;

    size_t hb = ((size_t)win * NHEAD + head) * NTOK * DH;
    const float* Qg = g_q + hb + (size_t)(qt * 64) * DH;

    // stage scaled Q, build persistent A fragments
    for (int idx = t; idx < 1024; idx += 128) {
        int r = idx >> 4, c4 = idx & 15;
        float4 v = *(const float4*)(Qg + (size_t)r * DH + c4 * 4);
        v.x *= 0.125f; v.y *= 0.125f; v.z *= 0.125f; v.w *= 0.125f;
        *(float4*)&sK[r * 72 + c4 * 4] = v;
    }
    __syncthreads();
    uint32_t qa[8][4];
    #pragma unroll
    for (int j = 0; j < 8; j++) {
        qa[j][0] = f2tf32(sK[(q0w + lq) * 72 + j * 8 + lr]);
        qa[j][1] = f2tf32(sK[(q0w + lq + 8) * 72 + j * 8 + lr]);
        qa[j][2] = f2tf32(sK[(q0w + lq) * 72 + j * 8 + lr + 4]);
        qa[j][3] = f2tf32(sK[(q0w + lq + 8) * 72 + j * 8 + lr + 4]);
    }
    __syncthreads();

    float m0 = -1e30f, m1 = -1e30f, l0 = 0.f, l1 = 0.f;
    float oa[8][4];
    #pragma unroll
    for (int nv = 0; nv < 8; nv++)
        #pragma unroll
        for (int r = 0; r < 4; r++) oa[nv][r] = 0.f;

    for (int kt = 0; kt < 16; kt++) {
        const float* Kg = g_k + hb + (size_t)(kt * 64) * DH;
        const float* Vg = g_v + hb + (size_t)(kt * 64) * DH;
        for (int idx = t; idx < 1024; idx += 128) {
            int r = idx >> 4, c4 = idx & 15;
            float4 k4 = *(const float4*)(Kg + (size_t)r * DH + c4 * 4);
            float4 v4 = *(const float4*)(Vg + (size_t)r * DH + c4 * 4);
            uint32_t* pk = (uint32_t*)&sK[r * 72 + c4 * 4];
            uint32_t* pv = (uint32_t*)&sV[r * 72 + c4 * 4];
            pk[0] = f2tf32(k4.x); pk[1] = f2tf32(k4.y);
            pk[2] = f2tf32(k4.z); pk[3] = f2tf32(k4.w);
            pv[0] = f2tf32(v4.x); pv[1] = f2tf32(v4.y);
            pv[2] = f2tf32(v4.z); pv[3] = f2tf32(v4.w);
        }
        __syncthreads();

        // S = Q K^T  (64 k-cols)
        float sc[8][4];
        #pragma unroll
        for (int nj = 0; nj < 8; nj++)
            #pragma unroll
            for (int r = 0; r < 4; r++) sc[nj][r] = 0.f;
        #pragma unroll
        for (int j2 = 0; j2 < 8; j2++) {
            #pragma unroll
            for (int nj = 0; nj < 8; nj++) {
                uint32_t b[2];
                b[0] = __float_as_uint(sK[(nj * 8 + lq) * 72 + j2 * 8 + lr]);
                b[1] = __float_as_uint(sK[(nj * 8 + lq) * 72 + j2 * 8 + lr + 4]);
                mma_tf32(sc[nj], qa[j2], b);
            }
        }

        // online softmax: rows lq (regs 0,1) and lq+8 (regs 2,3)
        float mx0 = -1e30f, mx1 = -1e30f;
        #pragma unroll
        for (int nj = 0; nj < 8; nj++) {
            mx0 = fmaxf(mx0, fmaxf(sc[nj][0], sc[nj][1]));
            mx1 = fmaxf(mx1, fmaxf(sc[nj][2], sc[nj][3]));
        }
        mx0 = fmaxf(mx0, __shfl_xor_sync(0xffffffffu, mx0, 1));
        mx0 = fmaxf(mx0, __shfl_xor_sync(0xffffffffu, mx0, 2));
        mx1 = fmaxf(mx1, __shfl_xor_sync(0xffffffffu, mx1, 1));
        mx1 = fmaxf(mx1, __shfl_xor_sync(0xffffffffu, mx1, 2));
        float mn0 = fmaxf(m0, mx0), mn1 = fmaxf(m1, mx1);
        float s0 = 0.f, s1 = 0.f;
        #pragma unroll
        for (int nj = 0; nj < 8; nj++) {
            sc[nj][0] = __expf(sc[nj][0] - mn0); s0 += sc[nj][0];
            sc[nj][1] = __expf(sc[nj][1] - mn0); s0 += sc[nj][1];
            sc[nj][2] = __expf(sc[nj][2] - mn1); s1 += sc[nj][2];
            sc[nj][3] = __expf(sc[nj][3] - mn1); s1 += sc[nj][3];
        }
        s0 += __shfl_xor_sync(0xffffffffu, s0, 1);
        s0 += __shfl_xor_sync(0xffffffffu, s0, 2);
        s1 += __shfl_xor_sync(0xffffffffu, s1, 1);
        s1 += __shfl_xor_sync(0xffffffffu, s1, 2);
        float al0 = __expf(m0 - mn0), al1 = __expf(m1 - mn1);
        l0 = l0 * al0 + s0; l1 = l1 * al1 + s1;
        m0 = mn0; m1 = mn1;
        #pragma unroll
        for (int nv = 0; nv < 8; nv++) {
            oa[nv][0] *= al0; oa[nv][1] *= al0;
            oa[nv][2] *= al1; oa[nv][3] *= al1;
        }

        // O += P V : quad-shuffle C-frag -> A-frag, then mma over d-blocks
        #pragma unroll
        for (int j = 0; j < 8; j++) {
            int src0 = (lane & ~3) | (lr >> 1);
            int src1 = src0 + 2;
            float v00 = __shfl_sync(0xffffffffu, sc[j][0], src0);
            float v01 = __shfl_sync(0xffffffffu, sc[j][1], src0);
            float v10 = __shfl_sync(0xffffffffu, sc[j][2], src0);
            float v11 = __shfl_sync(0xffffffffu, sc[j][3], src0);
            float w00 = __shfl_sync(0xffffffffu, sc[j][0], src1);
            float w01 = __shfl_sync(0xffffffffu, sc[j][1], src1);
            float w10 = __shfl_sync(0xffffffffu, sc[j][2], src1);
            float w11 = __shfl_sync(0xffffffffu, sc[j][3], src1);
            bool odd = (lr & 1);
            uint32_t pa[4];
            pa[0] = f2tf32(odd ? v01 : v00);
            pa[1] = f2tf32(odd ? v11 : v10);
            pa[2] = f2tf32(odd ? w01 : w00);
            pa[3] = f2tf32(odd ? w11 : w10);
            #pragma unroll
            for (int nv = 0; nv < 8; nv++) {
                uint32_t b[2];
                b[0] = __float_as_uint(sV[(j * 8 + lr) * 72 + nv * 8 + lq]);
                b[1] = __float_as_uint(sV[(j * 8 + lr + 4) * 72 + nv * 8 + lq]);
                mma_tf32(oa[nv], pa, b);
            }
        }
        __syncthreads();
    }

    // finalize + stage + token-major write
    float inv0 = 1.f / l0, inv1 = 1.f / l1;
    float* sOut = sK;   // [64][65]
    #pragma unroll
    for (int nv = 0; nv < 8; nv++) {
        sOut[(q0w + lq) * 65 + nv * 8 + 2 * lr]         = oa[nv][0] * inv0;
        sOut[(q0w + lq) * 65 + nv * 8 + 2 * lr + 1]     = oa[nv][1] * inv0;
        sOut[(q0w + lq + 8) * 65 + nv * 8 + 2 * lr]     = oa[nv][2] * inv1;
        sOut[(q0w + lq + 8) * 65 + nv * 8 + 2 * lr + 1] = oa[nv][3] * inv1;
    }
    __syncthreads();
    size_t tb = ((size_t)win * NTOK + qt * 64) * CCH + head * DH;
    for (int idx = t; idx < 4096; idx += 128) {
        int r = idx >> 6, d = idx & 63;
        g_aoT[tb + (size_t)r * CCH + d] = sOut[r * 65 + d];
    }
}

// ---------------------------------------------------------------------------
// Kernel 4: out projection, mma.sync tf32, pipelined + bias + residual.
// grid = (128 n-tiles, 4 m-tiles), 256 threads.
// ---------------------------------------------------------------------------
__global__ __launch_bounds__(256) void oproj_mma_kernel(
    const float* __restrict__ x, const float* __restrict__ wo,
    const float* __restrict__ bo, float* __restrict__ out) {
    __shared__ __align__(16) float sA[128 * 36];
    __shared__ __align__(16) float sB[128 * 36];

    int t = threadIdx.x, lane = t & 31, wid = t >> 5;
    int wrow = wid & 1, wcol = wid >> 1;
    int nt = blockIdx.x, mt = blockIdx.y;

    int o0  = mt * 128;
    int win = nt >> 3;
    int n0  = (nt & 7) * 128;
    int b   = win >> 2, wh = (win >> 1) & 1, ww = win & 1;
    const float* W = wo + (size_t)o0 * CCH;
    const float* X = g_aoT + (size_t)(win * NTOK + n0) * CCH;

    float acc[4][4][4];
    #pragma unroll
    for (int i = 0; i < 4; i++)
        #pragma unroll
        for (int j = 0; j < 4; j++)
            #pragma unroll
            for (int r = 0; r < 4; r++) acc[i][j][r] = 0.f;

    int lrow = t >> 3, lc4 = t & 7;
    int lq = lane >> 2, lr = lane & 3;

    float4 pa4[4], pb4[4];
    #pragma unroll
    for (int i = 0; i < 4; i++) {
        int row = lrow + i * 32;
        pa4[i] = *(const float4*)(W + (size_t)row * CCH + lc4 * 4);
        pb4[i] = *(const float4*)(X + (size_t)row * CCH + lc4 * 4);
    }

    for (int chunk = 0; chunk < 16; chunk++) {
        #pragma unroll
        for (int i = 0; i < 4; i++) {
            int row = lrow + i * 32;
            uint32_t* pa = (uint32_t*)&sA[row * 36 + lc4 * 4];
            uint32_t* pb = (uint32_t*)&sB[row * 36 + lc4 * 4];
            pa[0] = f2tf32(pa4[i].x); pa[1] = f2tf32(pa4[i].y);
            pa[2] = f2tf32(pa4[i].z); pa[3] = f2tf32(pa4[i].w);
            pb[0] = f2tf32(pb4[i].x); pb[1] = f2tf32(pb4[i].y);
            pb[2] = f2tf32(pb4[i].z); pb[3] = f2tf32(pb4[i].w);
        }
        if (chunk < 15) {
            int c0n = (chunk + 1) * 32;
            #pragma unroll
            for (int i = 0; i < 4; i++) {
                int row = lrow + i * 32;
                pa4[i] = *(const float4*)(W + (size_t)row * CCH + c0n + lc4 * 4);
                pb4[i] = *(const float4*)(X + (size_t)row * CCH + c0n + lc4 * 4);
            }
        }
        __syncthreads();
        #pragma unroll
        for (int ks = 0; ks < 4; ks++) {
            int k0 = ks * 8;
            uint32_t af[4][4], bf[4][2];
            #pragma unroll
            for (int mi = 0; mi < 4; mi++) {
                int m = wrow * 64 + mi * 16 + lq;
                af[mi][0] = __float_as_uint(sA[m * 36 + k0 + lr]);
                af[mi][1] = __float_as_uint(sA[(m + 8) * 36 + k0 + lr]);
                af[mi][2] = __float_as_uint(sA[m * 36 + k0 + lr + 4]);
                af[mi][3] = __float_as_uint(sA[(m + 8) * 36 + k0 + lr + 4]);
            }
            #pragma unroll
            for (int ni = 0; ni < 4; ni++) {
                int nn = wcol * 32 + ni * 8 + lq;
                bf[ni][0] = __float_as_uint(sB[nn * 36 + k0 + lr]);
                bf[ni][1] = __float_as_uint(sB[nn * 36 + k0 + lr + 4]);
            }
            #pragma unroll
            for (int mi = 0; mi < 4; mi++)
                #pragma unroll
                for (int ni = 0; ni < 4; ni++)
                    mma_tf32(acc[mi][ni], af[mi], bf[ni]);
        }
        __syncthreads();
    }

    float* sT = sA;   // [128 o][36]
    for (int cb = 0; cb < 4; cb++) {
        if (wcol == cb) {
            #pragma unroll
            for (int mi = 0; mi < 4; mi++) {
                int ob = wrow * 64 + mi * 16 + lq;
                #pragma unroll
                for (int ni = 0; ni < 4; ni++) {
                    int nb = ni * 8 + 2 * lr;
                    sT[ob * 36 + nb]           = acc[mi][ni][0];
                    sT[ob * 36 + nb + 1]       = acc[mi][ni][1];
                    sT[(ob + 8) * 36 + nb]     = acc[mi][ni][2];
                    sT[(ob + 8) * 36 + nb + 1] = acc[mi][ni][3];
                }
            }
        }
        __syncthreads();

        int nb = n0 + cb * 32;
        int w1 = nb >> 5;
        int h  = wh * 32 + (w1 & 31);
        for (int idx = t; idx < 1024; idx += 256) {
            int o = idx >> 3, f4 = idx & 7;
            float4 v = *(const float4*)&sT[o * 36 + f4 * 4];
            float bval = bo[o0 + o];
            size_t ga = ((size_t)(b * CCH + o0 + o) * HW) + h * 64 + ww * 32 + f4 * 4;
            float4 xr = *(const float4*)(x + ga);
            v.x += bval + xr.x; v.y += bval + xr.y;
            v.z += bval + xr.z; v.w += bval + xr.w;
            *(float4*)(out + ga) = v;
        }
        __syncthreads();
    }
}

// ---------------------------------------------------------------------------
extern "C" void kernel_launch(void* const* d_in, const int* in_sizes, int n_in,
                              void* d_out, int out_size) {
    (void)in_sizes; (void)n_in; (void)out_size;
    const float* x  = (const float*)d_in[0];
    const float* ns = (const float*)d_in[1];
    const float* nb = (const float*)d_in[2];
    const float* wq = (const float*)d_in[3];
    const float* bq = (const float*)d_in[4];
    const float* wk = (const float*)d_in[5];
    const float* bk = (const float*)d_in[6];
    const float* wv = (const float*)d_in[7];
    const float* bv = (const float*)d_in[8];
    const float* wo = (const float*)d_in[9];
    const float* bo = (const float*)d_in[10];
    float* out = (float*)d_out;

    gn_kernel<<<128, 256>>>(x, ns, nb);
    qkv_mma_kernel<<<dim3(128, 12), 256>>>(wq, bq, wk, bk, wv, bv);
    attn_mma_kernel<<<dim3(16, 8, 16), 128>>>();
    oproj_mma_kernel<<<dim3(128, 4), 256>>>(x, wo, bo, out);
}